// round 4
// baseline (speedup 1.0000x reference)
#include <cuda_runtime.h>
#include <cuda_fp16.h>
#include <mma.h>
#include <stdint.h>
#include <math.h>

using namespace nvcuda;

#define NTOK 8192
#define DIM  1024
#define HID  4096
#define NE   8
#define BM   128
#define BN   128
#define BK   32
#define LDSMW (BK + 8)
#define GM   4
#define PAD  (GM*BM)
#define MAXG 24
#define MAXT (NTOK / BM + NE)
#define SMEM_BYTES (1024 + 1024 + 2*GM*16384 + 2*16384)

// arch-specific ('a') feature detection: tcgen05 legal only in these passes
#if defined(__CUDA_ARCH_FEAT_SM103_ALL) || defined(__CUDA_ARCH_FEAT_SM100_ALL) || defined(__CUDA_ARCH_FEAT_SM101_ALL)
#define TC5 1
#else
#define TC5 0
#endif

// ---------------- device scratch ----------------
__device__ int    g_expert[NTOK];
__device__ int    g_count[NE];
__device__ int    g_cursor[NE];
__device__ int    g_off[NE + 1];
__device__ int    g_perm[NTOK];
__device__ int    g_grp_e[MAXG];
__device__ int    g_grp_r0[MAXG];
__device__ int    g_grp_ng[MAXG];
__device__ int    g_tile_e[MAXT];
__device__ int    g_tile_r0[MAXT];
__device__ __half g_xg[(size_t)(NTOK + PAD) * DIM];
__device__ __half g_h [(size_t)(NTOK + PAD) * HID];

// ---------------- PTX helpers ----------------
__device__ __forceinline__ uint32_t smem_u32(const void* p) {
    uint32_t a;
    asm("{ .reg .u64 t; cvta.to.shared.u64 t, %1; cvt.u32.u64 %0, t; }" : "=r"(a) : "l"(p));
    return a;
}
#if TC5
__device__ __forceinline__ bool elect1() {
    uint32_t r;
    asm volatile("{\n\t.reg .pred p;\n\telect.sync _|p, 0xFFFFFFFF;\n\tselp.b32 %0,1,0,p;\n\t}" : "=r"(r));
    return r != 0;
}
__device__ __forceinline__ void mbar_init(uint32_t a, uint32_t cnt) {
    asm volatile("mbarrier.init.shared.b64 [%0], %1;" :: "r"(a), "r"(cnt) : "memory");
}
__device__ __forceinline__ void mbar_wait(uint32_t a, uint32_t ph) {
    asm volatile(
        "{\n\t.reg .pred P;\n\t"
        "LW_%=:\n\t"
        "mbarrier.try_wait.parity.acquire.cta.shared::cta.b64 P, [%0], %1, 0x989680;\n\t"
        "@P bra LD_%=;\n\t"
        "bra LW_%=;\n\t"
        "LD_%=:\n\t}"
        :: "r"(a), "r"(ph) : "memory");
}
__device__ __forceinline__ void tmalloc(uint32_t smem_dst, uint32_t ncols) {
    asm volatile("tcgen05.alloc.cta_group::1.sync.aligned.shared::cta.b32 [%0], %1;"
                 :: "r"(smem_dst), "r"(ncols) : "memory");
}
__device__ __forceinline__ void tmdealloc(uint32_t tmem, uint32_t ncols) {
    asm volatile("tcgen05.relinquish_alloc_permit.cta_group::1.sync.aligned;");
    asm volatile("tcgen05.dealloc.cta_group::1.sync.aligned.b32 %0, %1;" :: "r"(tmem), "r"(ncols));
}
__device__ __forceinline__ void mma_f16_ss(uint32_t d, uint64_t ad, uint64_t bd, uint32_t idesc, uint32_t en) {
    asm volatile(
        "{\n\t.reg .pred p;\n\tsetp.ne.u32 p, %5, 0;\n\t"
        "tcgen05.mma.cta_group::1.kind::f16 [%0], %1, %2, %3, {%4,%4,%4,%4}, p;\n\t}"
        :: "r"(d), "l"(ad), "l"(bd), "r"(idesc), "r"(0u), "r"(en) : "memory");
}
__device__ __forceinline__ void tccommit(uint32_t mbar) {
    asm volatile("tcgen05.commit.cta_group::1.mbarrier::arrive::one.shared::cluster.b64 [%0];"
                 :: "r"(mbar) : "memory");
}
__device__ __forceinline__ void cpa16(uint32_t dst, const void* src) {
    asm volatile("cp.async.cg.shared.global [%0], [%1], 16;" :: "r"(dst), "l"(src) : "memory");
}
__device__ __forceinline__ void ldtm32(uint32_t* r, uint32_t addr) {
    asm volatile(
        "tcgen05.ld.sync.aligned.32x32b.x32.b32 "
        "{%0, %1, %2, %3, %4, %5, %6, %7, "
        " %8, %9, %10, %11, %12, %13, %14, %15, "
        " %16, %17, %18, %19, %20, %21, %22, %23, "
        " %24, %25, %26, %27, %28, %29, %30, %31}, [%32];"
        : "=r"(r[0]),  "=r"(r[1]),  "=r"(r[2]),  "=r"(r[3]),
          "=r"(r[4]),  "=r"(r[5]),  "=r"(r[6]),  "=r"(r[7]),
          "=r"(r[8]),  "=r"(r[9]),  "=r"(r[10]), "=r"(r[11]),
          "=r"(r[12]), "=r"(r[13]), "=r"(r[14]), "=r"(r[15]),
          "=r"(r[16]), "=r"(r[17]), "=r"(r[18]), "=r"(r[19]),
          "=r"(r[20]), "=r"(r[21]), "=r"(r[22]), "=r"(r[23]),
          "=r"(r[24]), "=r"(r[25]), "=r"(r[26]), "=r"(r[27]),
          "=r"(r[28]), "=r"(r[29]), "=r"(r[30]), "=r"(r[31])
        : "r"(addr));
}
#endif
#define SWZ(o) ((o) ^ (((o) >> 3) & 0x70))
__device__ __forceinline__ uint64_t mk_desc(uint32_t addr) {
    return ((uint64_t)2 << 61) | ((uint64_t)1 << 46) | ((uint64_t)64 << 32) |
           ((uint64_t)1 << 16) | ((addr >> 4) & 0x3FFF);
}

// ---------------- init ----------------
__global__ void k_init() {
    int i = threadIdx.x;
    if (i < NE) { g_count[i] = 0; g_cursor[i] = 0; }
}

// ---------------- router ----------------
__global__ void k_router(const float* __restrict__ x,
                         const float* __restrict__ Wr,
                         const float* __restrict__ br) {
    __shared__ float sW[NE * DIM];
    for (int i = threadIdx.x; i < NE * DIM; i += 256) sW[i] = Wr[i];
    __syncthreads();

    int warp = threadIdx.x >> 5, lane = threadIdx.x & 31;
    int t = blockIdx.x * 8 + warp;
    const float4* xr = (const float4*)(x + (size_t)t * DIM);

    float acc[NE];
#pragma unroll
    for (int e = 0; e < NE; e++) acc[e] = 0.f;
#pragma unroll
    for (int p = 0; p < 8; p++) {
        float4 v = xr[p * 32 + lane];
        int c = (p * 32 + lane) * 4;
#pragma unroll
        for (int e = 0; e < NE; e++) {
            const float* w = &sW[e * DIM + c];
            acc[e] += v.x * w[0] + v.y * w[1] + v.z * w[2] + v.w * w[3];
        }
    }
#pragma unroll
    for (int e = 0; e < NE; e++)
#pragma unroll
        for (int o = 16; o; o >>= 1) acc[e] += __shfl_xor_sync(0xffffffffu, acc[e], o);

    if (lane == 0) {
        int best = 0;
        float bv = acc[0] + br[0];
#pragma unroll
        for (int e = 1; e < NE; e++) {
            float v = acc[e] + br[e];
            if (v > bv) { bv = v; best = e; }
        }
        g_expert[t] = best;
        atomicAdd(&g_count[best], 1);
    }
}

// ---------------- scan ----------------
__global__ void k_scan() {
    if (threadIdx.x != 0) return;
    int o = 0;
    for (int e = 0; e < NE; e++) { g_off[e] = o; o += g_count[e]; }
    g_off[NE] = o;
    int t = 0;
    for (int e = 0; e < NE; e++) {
        int tiles = (g_count[e] + BM - 1) / BM;
        for (int m = 0; m < tiles; m += GM) {
            g_grp_e[t] = e;
            g_grp_r0[t] = g_off[e] + m * BM;
            int rem = tiles - m;
            g_grp_ng[t] = rem < GM ? rem : GM;
            t++;
        }
    }
    for (; t < MAXG; t++) g_grp_e[t] = -1;
    int tt = 0;
    for (int e = 0; e < NE; e++) {
        int tiles = (g_count[e] + BM - 1) / BM;
        for (int m = 0; m < tiles; m++) { g_tile_e[tt] = e; g_tile_r0[tt] = g_off[e] + m * BM; tt++; }
    }
    for (; tt < MAXT; tt++) g_tile_e[tt] = -1;
}

// ---------------- gather + fp32->fp16 ----------------
__global__ void k_gather(const float* __restrict__ x) {
    int gw = (blockIdx.x * blockDim.x + threadIdx.x) >> 5;
    int lane = threadIdx.x & 31;
    if (gw >= NTOK) return;
    int t = gw, e = g_expert[t];
    int slot = 0;
    if (lane == 0) {
        int r = atomicAdd(&g_cursor[e], 1);
        slot = g_off[e] + r;
        g_perm[slot] = t;
    }
    slot = __shfl_sync(0xffffffffu, slot, 0);
    const float4* src = (const float4*)(x + (size_t)t * DIM);
    __half2* dst = (__half2*)(g_xg + (size_t)slot * DIM);
#pragma unroll
    for (int p = 0; p < 8; p++) {
        float4 v = src[p * 32 + lane];
        dst[(p * 32 + lane) * 2]     = __floats2half2_rn(v.x, v.y);
        dst[(p * 32 + lane) * 2 + 1] = __floats2half2_rn(v.z, v.w);
    }
}

// ================= tcgen05 grouped GEMM, software-pipelined loads =================
template<int KTOT, bool UP>
__global__ void __launch_bounds__(256, 1) k_gemm(const float* __restrict__ W,
                                                 const float* __restrict__ bias,
                                                 float* __restrict__ out) {
#if TC5
    extern __shared__ char smem_raw[];
    char* smem = (char*)(((uintptr_t)smem_raw + 1023) & ~(uintptr_t)1023);
    const int NOUT = UP ? HID : DIM;

    int gi = blockIdx.y;
    int e = g_grp_e[gi];
    if (e < 0) return;
    int row0 = g_grp_r0[gi], ng = g_grp_ng[gi], row_end = g_off[e + 1];
    int n0 = blockIdx.x * BN;
    int tid = threadIdx.x, warp = tid >> 5, lane = tid & 31;
    uint32_t sb = smem_u32(smem);

    if (tid == 0) { mbar_init(sb + 0, 1); mbar_init(sb + 8, 1); }
    if (warp == 0) tmalloc(sb + 16, 512);
    __syncthreads();
    uint32_t tmem;
    asm volatile("ld.shared.b32 %0, [%1];" : "=r"(tmem) : "r"(sb + 16));

    const __half* Asrc = UP ? g_xg : g_h;
    const __half* Ag = Asrc + (size_t)row0 * KTOT;
    const float*  Bg = W + (size_t)e * NOUT * KTOT + (size_t)n0 * KTOT;
    const uint32_t idesc = (1u << 4) | ((BN / 8) << 17) | ((BM / 16) << 24);

    const int SMA = 1024;
    const int SMB = 1024 + 2 * GM * 16384;

    // ---- pipelined load helpers ----
    float4 rB[2][8];
    auto CPA_A = [&](int s, int buf) {
        uint32_t aBase = sb + SMA + buf * (GM * 16384);
#pragma unroll
        for (int g = 0; g < GM; g++) {
            if (g < ng) {
                const __half* As = Ag + (size_t)g * BM * KTOT + s * 64;
                uint32_t dstb = aBase + g * 16384;
#pragma unroll
                for (int i = 0; i < 4; i++) {
                    int q = tid + i * 256;
                    int r = q >> 3, c = q & 7;
                    cpa16(dstb + SWZ((uint32_t)(r * 128 + c * 16)),
                          As + (size_t)r * KTOT + c * 8);
                }
            }
        }
        asm volatile("cp.async.commit_group;" ::: "memory");
    };
    auto LDG_B = [&](int s, float4* r) {
        const float* Bs = Bg + s * 64;
#pragma unroll
        for (int i = 0; i < 8; i++) {
            int q = tid + i * 256;
            int rr = q >> 4, c4 = q & 15;
            r[i] = *(const float4*)(Bs + (size_t)rr * KTOT + c4 * 4);
        }
    };
    auto STS_B = [&](int buf, float4* r) {
        char* bb = smem + SMB + buf * 16384;
#pragma unroll
        for (int i = 0; i < 8; i++) {
            int q = tid + i * 256;
            int rr = q >> 4, c4 = q & 15;
            __half2 h0 = __floats2half2_rn(r[i].x, r[i].y);
            __half2 h1 = __floats2half2_rn(r[i].z, r[i].w);
            uint2 pk;
            pk.x = *(uint32_t*)&h0;
            pk.y = *(uint32_t*)&h1;
            uint32_t off = SWZ((uint32_t)(rr * 128 + (c4 >> 1) * 16)) + (c4 & 1) * 8;
            *(uint2*)(bb + off) = pk;
        }
    };

    uint32_t ph[2] = {0, 0};
    const int NKC = KTOT / 64;

    // prologue: stage 0 in flight
    CPA_A(0, 0);
    LDG_B(0, rB[0]);

    for (int s = 0; s < NKC; s++) {
        int buf = s & 1;
        int cur = s & 1, nxt = cur ^ 1;
        if (s + 1 < NKC) {
            if (s + 1 >= 2) { mbar_wait(sb + 8 * ((s + 1) & 1), ph[(s + 1) & 1]); ph[(s + 1) & 1] ^= 1; }
            CPA_A(s + 1, buf ^ 1);     // next A stage in flight
            LDG_B(s + 1, rB[nxt]);     // next B in registers (latency spans iteration)
        }
        STS_B(buf, rB[cur]);
        if (s + 1 < NKC) asm volatile("cp.async.wait_group 1;" ::: "memory");
        else             asm volatile("cp.async.wait_group 0;" ::: "memory");
        asm volatile("fence.proxy.async.shared::cta;" ::: "memory");
        __syncthreads();

        if (warp == 0 && elect1()) {
            uint32_t aBase = sb + SMA + buf * (GM * 16384);
            uint64_t bd0 = mk_desc(sb + SMB + buf * 16384);
#pragma unroll
            for (int g = 0; g < GM; g++) {
                if (g < ng) {
                    uint64_t ad0 = mk_desc(aBase + g * 16384);
#pragma unroll
                    for (int ks = 0; ks < 4; ks++) {
                        mma_f16_ss(tmem + g * BN, ad0 + ks * 2, bd0 + ks * 2, idesc,
                                   (uint32_t)((s | ks) != 0));
                    }
                }
            }
            tccommit(sb + 8 * buf);
        }
    }
    mbar_wait(sb + 0, ph[0]);
    mbar_wait(sb + 8, ph[1]);
    asm volatile("tcgen05.fence::after_thread_sync;" ::: "memory");

    // ---- epilogue ----
    int sub = warp & 3;
    int hset = warp >> 2;
    const float* bp = bias + (size_t)e * NOUT + n0;
#pragma unroll
    for (int gg = 0; gg < 2; gg++) {
        int g = hset * 2 + gg;
        if (g >= ng) continue;
        int row = row0 + g * BM + sub * 32 + lane;
        bool ok = row < row_end;
#pragma unroll
        for (int cb = 0; cb < 4; cb++) {
            uint32_t r[32];
            ldtm32(r, tmem + g * BN + cb * 32);
            asm volatile("tcgen05.wait::ld.sync.aligned;" ::: "memory");
            if (ok) {
                int col = cb * 32;
                if (UP) {
                    __half2 o[16];
#pragma unroll
                    for (int j = 0; j < 16; j++) {
                        float v0 = __uint_as_float(r[2 * j])     + bp[col + 2 * j];
                        float v1 = __uint_as_float(r[2 * j + 1]) + bp[col + 2 * j + 1];
                        v0 = v0 / (1.f + __expf(-v0));
                        v1 = v1 / (1.f + __expf(-v1));
                        o[j] = __floats2half2_rn(v0, v1);
                    }
                    int4* dst = (int4*)(g_h + (size_t)row * HID + n0 + col);
#pragma unroll
                    for (int q = 0; q < 4; q++) dst[q] = ((int4*)o)[q];
                } else {
                    int tok = g_perm[row];
                    float4* dst = (float4*)(out + (size_t)tok * DIM + n0 + col);
#pragma unroll
                    for (int q = 0; q < 8; q++) {
                        float4 ov;
                        ov.x = __uint_as_float(r[4 * q + 0]) + bp[col + 4 * q + 0];
                        ov.y = __uint_as_float(r[4 * q + 1]) + bp[col + 4 * q + 1];
                        ov.z = __uint_as_float(r[4 * q + 2]) + bp[col + 4 * q + 2];
                        ov.w = __uint_as_float(r[4 * q + 3]) + bp[col + 4 * q + 3];
                        dst[q] = ov;
                    }
                }
            }
        }
    }
    __syncthreads();
    if (warp == 0) tmdealloc(tmem, 512);
#endif
}

// ================= wmma fallback GEMMs (active only in non-'a' image) =================
__global__ __launch_bounds__(256, 2) void k_up(const float* __restrict__ Wup,
                                               const float* __restrict__ bup) {
#if !TC5
    __shared__ __align__(128) char smem_raw[4 * BM * LDSMW * sizeof(__half)];
    __half (*sA)[BM][LDSMW] = (__half (*)[BM][LDSMW])smem_raw;
    __half (*sB)[BM][LDSMW] = (__half (*)[BM][LDSMW])(smem_raw + 2 * BM * LDSMW * sizeof(__half));
    float* stage_all = (float*)smem_raw;

    int mt = blockIdx.y;
    int e = g_tile_e[mt];
    if (e < 0) return;
    int row0 = g_tile_r0[mt], row_end = g_off[e + 1];
    int n0 = blockIdx.x * BN;
    int tid = threadIdx.x, warp = tid >> 5, lane = tid & 31;
    int wm = warp >> 2, wn = warp & 3;

    const __half* Ag = g_xg + (size_t)row0 * DIM;
    const float*  Bg = Wup + (size_t)e * HID * DIM + (size_t)n0 * DIM;

    wmma::fragment<wmma::accumulator, 16, 16, 16, float> c[4][2];
#pragma unroll
    for (int i = 0; i < 4; i++)
#pragma unroll
        for (int j = 0; j < 2; j++) wmma::fill_fragment(c[i][j], 0.f);

    int4 ra[2];
    float4 rb[4];

    auto LOADA = [&](int kt) {
#pragma unroll
        for (int i = 0; i < 2; i++) {
            int q = tid + i * 256, r = q >> 2, c8 = q & 3;
            ra[i] = *(const int4*)(Ag + (size_t)r * DIM + kt * BK + c8 * 8);
        }
    };
    auto LOADB = [&](int kt) {
#pragma unroll
        for (int i = 0; i < 4; i++) {
            int q = tid + i * 256, r = q >> 3, c4 = q & 7;
            rb[i] = *(const float4*)(Bg + (size_t)r * DIM + kt * BK + c4 * 4);
        }
    };
    auto STORE = [&](int buf) {
#pragma unroll
        for (int i = 0; i < 2; i++) {
            int q = tid + i * 256, r = q >> 2, c8 = q & 3;
            *(int4*)&sA[buf][r][c8 * 8] = ra[i];
        }
#pragma unroll
        for (int i = 0; i < 4; i++) {
            int q = tid + i * 256, r = q >> 3, c4 = q & 7;
            *(__half2*)&sB[buf][r][c4 * 4]     = __floats2half2_rn(rb[i].x, rb[i].y);
            *(__half2*)&sB[buf][r][c4 * 4 + 2] = __floats2half2_rn(rb[i].z, rb[i].w);
        }
    };
    auto COMP = [&](int buf) {
#pragma unroll
        for (int ks = 0; ks < 2; ks++) {
            wmma::fragment<wmma::matrix_a, 16, 16, 16, __half, wmma::row_major> a[4];
            wmma::fragment<wmma::matrix_b, 16, 16, 16, __half, wmma::col_major> b[2];
#pragma unroll
            for (int i = 0; i < 4; i++)
                wmma::load_matrix_sync(a[i], &sA[buf][wm * 64 + i * 16][ks * 16], LDSMW);
#pragma unroll
            for (int j = 0; j < 2; j++)
                wmma::load_matrix_sync(b[j], &sB[buf][wn * 32 + j * 16][ks * 16], LDSMW);
#pragma unroll
            for (int i = 0; i < 4; i++)
#pragma unroll
                for (int j = 0; j < 2; j++)
                    wmma::mma_sync(c[i][j], a[i], b[j], c[i][j]);
        }
    };

    LOADA(0); LOADB(0); STORE(0); __syncthreads();
    const int NK = DIM / BK;
    for (int kt = 1; kt < NK; kt++) {
        LOADA(kt); LOADB(kt);
        COMP((kt - 1) & 1);
        STORE(kt & 1);
        __syncthreads();
    }
    COMP((NK - 1) & 1);
    __syncthreads();

    float* st = stage_all + warp * 16 * 20;
#pragma unroll
    for (int i = 0; i < 4; i++)
#pragma unroll
        for (int j = 0; j < 2; j++) {
            wmma::store_matrix_sync(st, c[i][j], 20, wmma::mem_row_major);
            __syncwarp();
            int rr = lane >> 1, cbase = (lane & 1) * 8;
            int grow = row0 + wm * 64 + i * 16 + rr;
            if (grow < row_end) {
                int gcol = n0 + wn * 32 + j * 16 + cbase;
                __half2 o[4];
#pragma unroll
                for (int k2 = 0; k2 < 4; k2++) {
                    float v0 = st[rr * 20 + cbase + 2 * k2]     + bup[(size_t)e * HID + gcol + 2 * k2];
                    float v1 = st[rr * 20 + cbase + 2 * k2 + 1] + bup[(size_t)e * HID + gcol + 2 * k2 + 1];
                    v0 = v0 / (1.f + expf(-v0));
                    v1 = v1 / (1.f + expf(-v1));
                    o[k2] = __floats2half2_rn(v0, v1);
                }
                *(int4*)&g_h[(size_t)grow * HID + gcol] = *(int4*)o;
            }
            __syncwarp();
        }
#endif
}

__global__ __launch_bounds__(256, 2) void k_down(const float* __restrict__ Wdown,
                                                 const float* __restrict__ bdown,
                                                 float* __restrict__ out) {
#if !TC5
    __shared__ __align__(128) char smem_raw[4 * BM * LDSMW * sizeof(__half)];
    __half (*sA)[BM][LDSMW] = (__half (*)[BM][LDSMW])smem_raw;
    __half (*sB)[BM][LDSMW] = (__half (*)[BM][LDSMW])(smem_raw + 2 * BM * LDSMW * sizeof(__half));
    float* stage_all = (float*)smem_raw;

    int mt = blockIdx.y;
    int e = g_tile_e[mt];
    if (e < 0) return;
    int row0 = g_tile_r0[mt], row_end = g_off[e + 1];
    int n0 = blockIdx.x * BN;
    int tid = threadIdx.x, warp = tid >> 5, lane = tid & 31;
    int wm = warp >> 2, wn = warp & 3;

    const __half* Ag = g_h + (size_t)row0 * HID;
    const float*  Bg = Wdown + (size_t)e * DIM * HID + (size_t)n0 * HID;

    wmma::fragment<wmma::accumulator, 16, 16, 16, float> c[4][2];
#pragma unroll
    for (int i = 0; i < 4; i++)
#pragma unroll
        for (int j = 0; j < 2; j++) wmma::fill_fragment(c[i][j], 0.f);

    int4 ra[2];
    float4 rb[4];

    auto LOADA = [&](int kt) {
#pragma unroll
        for (int i = 0; i < 2; i++) {
            int q = tid + i * 256, r = q >> 2, c8 = q & 3;
            ra[i] = *(const int4*)(Ag + (size_t)r * HID + kt * BK + c8 * 8);
        }
    };
    auto LOADB = [&](int kt) {
#pragma unroll
        for (int i = 0; i < 4; i++) {
            int q = tid + i * 256, r = q >> 3, c4 = q & 7;
            rb[i] = *(const float4*)(Bg + (size_t)r * HID + kt * BK + c4 * 4);
        }
    };
    auto STORE = [&](int buf) {
#pragma unroll
        for (int i = 0; i < 2; i++) {
            int q = tid + i * 256, r = q >> 2, c8 = q & 3;
            *(int4*)&sA[buf][r][c8 * 8] = ra[i];
        }
#pragma unroll
        for (int i = 0; i < 4; i++) {
            int q = tid + i * 256, r = q >> 3, c4 = q & 7;
            *(__half2*)&sB[buf][r][c4 * 4]     = __floats2half2_rn(rb[i].x, rb[i].y);
            *(__half2*)&sB[buf][r][c4 * 4 + 2] = __floats2half2_rn(rb[i].z, rb[i].w);
        }
    };
    auto COMP = [&](int buf) {
#pragma unroll
        for (int ks = 0; ks < 2; ks++) {
            wmma::fragment<wmma::matrix_a, 16, 16, 16, __half, wmma::row_major> a[4];
            wmma::fragment<wmma::matrix_b, 16, 16, 16, __half, wmma::col_major> b[2];
#pragma unroll
            for (int i = 0; i < 4; i++)
                wmma::load_matrix_sync(a[i], &sA[buf][wm * 64 + i * 16][ks * 16], LDSMW);
#pragma unroll
            for (int j = 0; j < 2; j++)
                wmma::load_matrix_sync(b[j], &sB[buf][wn * 32 + j * 16][ks * 16], LDSMW);
#pragma unroll
            for (int i = 0; i < 4; i++)
#pragma unroll
                for (int j = 0; j < 2; j++)
                    wmma::mma_sync(c[i][j], a[i], b[j], c[i][j]);
        }
    };

    LOADA(0); LOADB(0); STORE(0); __syncthreads();
    const int NK = HID / BK;
    for (int kt = 1; kt < NK; kt++) {
        LOADA(kt); LOADB(kt);
        COMP((kt - 1) & 1);
        STORE(kt & 1);
        __syncthreads();
    }
    COMP((NK - 1) & 1);
    __syncthreads();

    float* st = stage_all + warp * 16 * 20;
#pragma unroll
    for (int i = 0; i < 4; i++)
#pragma unroll
        for (int j = 0; j < 2; j++) {
            wmma::store_matrix_sync(st, c[i][j], 20, wmma::mem_row_major);
            __syncwarp();
            int rr = lane >> 1, cbase = (lane & 1) * 8;
            int grow = row0 + wm * 64 + i * 16 + rr;
            if (grow < row_end) {
                int tok = g_perm[grow];
                int gcol = n0 + wn * 32 + j * 16 + cbase;
                float4 o0, o1;
                o0.x = st[rr * 20 + cbase + 0] + bdown[(size_t)e * DIM + gcol + 0];
                o0.y = st[rr * 20 + cbase + 1] + bdown[(size_t)e * DIM + gcol + 1];
                o0.z = st[rr * 20 + cbase + 2] + bdown[(size_t)e * DIM + gcol + 2];
                o0.w = st[rr * 20 + cbase + 3] + bdown[(size_t)e * DIM + gcol + 3];
                o1.x = st[rr * 20 + cbase + 4] + bdown[(size_t)e * DIM + gcol + 4];
                o1.y = st[rr * 20 + cbase + 5] + bdown[(size_t)e * DIM + gcol + 5];
                o1.z = st[rr * 20 + cbase + 6] + bdown[(size_t)e * DIM + gcol + 6];
                o1.w = st[rr * 20 + cbase + 7] + bdown[(size_t)e * DIM + gcol + 7];
                *(float4*)&out[(size_t)tok * DIM + gcol]     = o0;
                *(float4*)&out[(size_t)tok * DIM + gcol + 4] = o1;
            }
            __syncwarp();
        }
#endif
}

// ---------------- launcher ----------------
extern "C" void kernel_launch(void* const* d_in, const int* in_sizes, int n_in,
                              void* d_out, int out_size) {
    const float* x     = (const float*)d_in[0];
    const float* Wr    = (const float*)d_in[1];
    const float* br    = (const float*)d_in[2];
    const float* Wup   = (const float*)d_in[3];
    const float* bup   = (const float*)d_in[4];
    const float* Wdown = (const float*)d_in[5];
    const float* bdown = (const float*)d_in[6];
    float* out = (float*)d_out;

    cudaFuncSetAttribute(k_gemm<DIM, true>,  cudaFuncAttributeMaxDynamicSharedMemorySize, SMEM_BYTES);
    cudaFuncSetAttribute(k_gemm<HID, false>, cudaFuncAttributeMaxDynamicSharedMemorySize, SMEM_BYTES);

    // launch order puts k_gemm<UP> at slot 6 for ncu -s 5 -c 1
    k_init<<<1, 32>>>();                                                       // 1
    k_router<<<NTOK / 8, 256>>>(x, Wr, br);                                    // 2
    k_scan<<<1, 1>>>();                                                        // 3
    k_gather<<<NTOK / 8, 256>>>(x);                                            // 4
    k_up<<<dim3(HID / BN, MAXT), 256>>>(Wup, bup);                             // 5 (empty in 'a')
    k_gemm<DIM, true ><<<dim3(HID / BN, MAXG), 256, SMEM_BYTES>>>(Wup, bup, nullptr);   // 6
    k_gemm<HID, false><<<dim3(DIM / BN, MAXG), 256, SMEM_BYTES>>>(Wdown, bdown, out);   // 7
    k_down<<<dim3(DIM / BN, MAXT), 256>>>(Wdown, bdown, out);                  // 8 (empty in 'a')
}

// round 5
// speedup vs baseline: 1.3334x; 1.3334x over previous
#include <cuda_runtime.h>
#include <cuda_fp16.h>
#include <mma.h>
#include <stdint.h>
#include <math.h>

using namespace nvcuda;

#define NTOK 8192
#define DIM  1024
#define HID  4096
#define NE   8
#define BM   128
#define BN   128
#define BK   32
#define LDSMW (BK + 8)
#define GM   4
#define PAD  (GM*BM)
#define MAXG 24
#define MAXT (NTOK / BM + NE)
#define SMEM_BYTES (1024 + 1024 + 2*GM*16384 + 2*16384)

// arch-specific ('a') feature detection: tcgen05 legal only in these passes
#if defined(__CUDA_ARCH_FEAT_SM103_ALL) || defined(__CUDA_ARCH_FEAT_SM100_ALL) || defined(__CUDA_ARCH_FEAT_SM101_ALL)
#define TC5 1
#else
#define TC5 0
#endif

// ---------------- device scratch ----------------
__device__ int    g_expert[NTOK];
__device__ int    g_count[NE];
__device__ int    g_cursor[NE];
__device__ int    g_off[NE + 1];
__device__ int    g_perm[NTOK];
__device__ int    g_grp_e[MAXG];
__device__ int    g_grp_r0[MAXG];
__device__ int    g_grp_ng[MAXG];
__device__ int    g_tile_e[MAXT];
__device__ int    g_tile_r0[MAXT];
__device__ __half g_xg[(size_t)(NTOK + PAD) * DIM];
__device__ __half g_h [(size_t)(NTOK + PAD) * HID];

// ---------------- PTX helpers ----------------
__device__ __forceinline__ uint32_t smem_u32(const void* p) {
    uint32_t a;
    asm("{ .reg .u64 t; cvta.to.shared.u64 t, %1; cvt.u32.u64 %0, t; }" : "=r"(a) : "l"(p));
    return a;
}
#if TC5
__device__ __forceinline__ bool elect1() {
    uint32_t r;
    asm volatile("{\n\t.reg .pred p;\n\telect.sync _|p, 0xFFFFFFFF;\n\tselp.b32 %0,1,0,p;\n\t}" : "=r"(r));
    return r != 0;
}
__device__ __forceinline__ void mbar_init(uint32_t a, uint32_t cnt) {
    asm volatile("mbarrier.init.shared.b64 [%0], %1;" :: "r"(a), "r"(cnt) : "memory");
}
__device__ __forceinline__ void mbar_wait(uint32_t a, uint32_t ph) {
    asm volatile(
        "{\n\t.reg .pred P;\n\t"
        "LW_%=:\n\t"
        "mbarrier.try_wait.parity.acquire.cta.shared::cta.b64 P, [%0], %1, 0x989680;\n\t"
        "@P bra LD_%=;\n\t"
        "bra LW_%=;\n\t"
        "LD_%=:\n\t}"
        :: "r"(a), "r"(ph) : "memory");
}
__device__ __forceinline__ void tmalloc(uint32_t smem_dst, uint32_t ncols) {
    asm volatile("tcgen05.alloc.cta_group::1.sync.aligned.shared::cta.b32 [%0], %1;"
                 :: "r"(smem_dst), "r"(ncols) : "memory");
}
__device__ __forceinline__ void tmdealloc(uint32_t tmem, uint32_t ncols) {
    asm volatile("tcgen05.relinquish_alloc_permit.cta_group::1.sync.aligned;");
    asm volatile("tcgen05.dealloc.cta_group::1.sync.aligned.b32 %0, %1;" :: "r"(tmem), "r"(ncols));
}
__device__ __forceinline__ void mma_f16_ss(uint32_t d, uint64_t ad, uint64_t bd, uint32_t idesc, uint32_t en) {
    asm volatile(
        "{\n\t.reg .pred p;\n\tsetp.ne.u32 p, %5, 0;\n\t"
        "tcgen05.mma.cta_group::1.kind::f16 [%0], %1, %2, %3, {%4,%4,%4,%4}, p;\n\t}"
        :: "r"(d), "l"(ad), "l"(bd), "r"(idesc), "r"(0u), "r"(en) : "memory");
}
__device__ __forceinline__ void tccommit(uint32_t mbar) {
    asm volatile("tcgen05.commit.cta_group::1.mbarrier::arrive::one.shared::cluster.b64 [%0];"
                 :: "r"(mbar) : "memory");
}
__device__ __forceinline__ void cpa16(uint32_t dst, const void* src) {
    asm volatile("cp.async.cg.shared.global [%0], [%1], 16;" :: "r"(dst), "l"(src) : "memory");
}
__device__ __forceinline__ void ldtm32(uint32_t* r, uint32_t addr) {
    asm volatile(
        "tcgen05.ld.sync.aligned.32x32b.x32.b32 "
        "{%0, %1, %2, %3, %4, %5, %6, %7, "
        " %8, %9, %10, %11, %12, %13, %14, %15, "
        " %16, %17, %18, %19, %20, %21, %22, %23, "
        " %24, %25, %26, %27, %28, %29, %30, %31}, [%32];"
        : "=r"(r[0]),  "=r"(r[1]),  "=r"(r[2]),  "=r"(r[3]),
          "=r"(r[4]),  "=r"(r[5]),  "=r"(r[6]),  "=r"(r[7]),
          "=r"(r[8]),  "=r"(r[9]),  "=r"(r[10]), "=r"(r[11]),
          "=r"(r[12]), "=r"(r[13]), "=r"(r[14]), "=r"(r[15]),
          "=r"(r[16]), "=r"(r[17]), "=r"(r[18]), "=r"(r[19]),
          "=r"(r[20]), "=r"(r[21]), "=r"(r[22]), "=r"(r[23]),
          "=r"(r[24]), "=r"(r[25]), "=r"(r[26]), "=r"(r[27]),
          "=r"(r[28]), "=r"(r[29]), "=r"(r[30]), "=r"(r[31])
        : "r"(addr));
}
#endif
#define SWZ(o) ((o) ^ (((o) >> 3) & 0x70))
__device__ __forceinline__ uint64_t mk_desc(uint32_t addr) {
    return ((uint64_t)2 << 61) | ((uint64_t)1 << 46) | ((uint64_t)64 << 32) |
           ((uint64_t)1 << 16) | ((addr >> 4) & 0x3FFF);
}

// ---------------- init ----------------
__global__ void k_init() {
    int i = threadIdx.x;
    if (i < NE) { g_count[i] = 0; g_cursor[i] = 0; }
}

// ---------------- router ----------------
__global__ void k_router(const float* __restrict__ x,
                         const float* __restrict__ Wr,
                         const float* __restrict__ br) {
    __shared__ float sW[NE * DIM];
    for (int i = threadIdx.x; i < NE * DIM; i += 256) sW[i] = Wr[i];
    __syncthreads();

    int warp = threadIdx.x >> 5, lane = threadIdx.x & 31;
    int t = blockIdx.x * 8 + warp;
    const float4* xr = (const float4*)(x + (size_t)t * DIM);

    float acc[NE];
#pragma unroll
    for (int e = 0; e < NE; e++) acc[e] = 0.f;
#pragma unroll
    for (int p = 0; p < 8; p++) {
        float4 v = xr[p * 32 + lane];
        int c = (p * 32 + lane) * 4;
#pragma unroll
        for (int e = 0; e < NE; e++) {
            const float* w = &sW[e * DIM + c];
            acc[e] += v.x * w[0] + v.y * w[1] + v.z * w[2] + v.w * w[3];
        }
    }
#pragma unroll
    for (int e = 0; e < NE; e++)
#pragma unroll
        for (int o = 16; o; o >>= 1) acc[e] += __shfl_xor_sync(0xffffffffu, acc[e], o);

    if (lane == 0) {
        int best = 0;
        float bv = acc[0] + br[0];
#pragma unroll
        for (int e = 1; e < NE; e++) {
            float v = acc[e] + br[e];
            if (v > bv) { bv = v; best = e; }
        }
        g_expert[t] = best;
        atomicAdd(&g_count[best], 1);
    }
}

// ---------------- scan ----------------
__global__ void k_scan() {
    if (threadIdx.x != 0) return;
    int o = 0;
    for (int e = 0; e < NE; e++) { g_off[e] = o; o += g_count[e]; }
    g_off[NE] = o;
    int t = 0;
    for (int e = 0; e < NE; e++) {
        int tiles = (g_count[e] + BM - 1) / BM;
        for (int m = 0; m < tiles; m += GM) {
            g_grp_e[t] = e;
            g_grp_r0[t] = g_off[e] + m * BM;
            int rem = tiles - m;
            g_grp_ng[t] = rem < GM ? rem : GM;
            t++;
        }
    }
    for (; t < MAXG; t++) g_grp_e[t] = -1;
    int tt = 0;
    for (int e = 0; e < NE; e++) {
        int tiles = (g_count[e] + BM - 1) / BM;
        for (int m = 0; m < tiles; m++) { g_tile_e[tt] = e; g_tile_r0[tt] = g_off[e] + m * BM; tt++; }
    }
    for (; tt < MAXT; tt++) g_tile_e[tt] = -1;
}

// ---------------- gather + fp32->fp16 ----------------
__global__ void k_gather(const float* __restrict__ x) {
    int gw = (blockIdx.x * blockDim.x + threadIdx.x) >> 5;
    int lane = threadIdx.x & 31;
    if (gw >= NTOK) return;
    int t = gw, e = g_expert[t];
    int slot = 0;
    if (lane == 0) {
        int r = atomicAdd(&g_cursor[e], 1);
        slot = g_off[e] + r;
        g_perm[slot] = t;
    }
    slot = __shfl_sync(0xffffffffu, slot, 0);
    const float4* src = (const float4*)(x + (size_t)t * DIM);
    __half2* dst = (__half2*)(g_xg + (size_t)slot * DIM);
#pragma unroll
    for (int p = 0; p < 8; p++) {
        float4 v = src[p * 32 + lane];
        dst[(p * 32 + lane) * 2]     = __floats2half2_rn(v.x, v.y);
        dst[(p * 32 + lane) * 2 + 1] = __floats2half2_rn(v.z, v.w);
    }
}

// ================= tcgen05 grouped GEMM: round-3 skeleton + reg-prefetched B =================
template<int KTOT, bool UP>
__global__ void __launch_bounds__(256, 1) k_gemm(const float* __restrict__ W,
                                                 const float* __restrict__ bias,
                                                 float* __restrict__ out) {
#if TC5
    extern __shared__ char smem_raw[];
    char* smem = (char*)(((uintptr_t)smem_raw + 1023) & ~(uintptr_t)1023);
    const int NOUT = UP ? HID : DIM;

    int gi = blockIdx.y;
    int e = g_grp_e[gi];
    if (e < 0) return;
    int row0 = g_grp_r0[gi], ng = g_grp_ng[gi], row_end = g_off[e + 1];
    int n0 = blockIdx.x * BN;
    int tid = threadIdx.x, warp = tid >> 5, lane = tid & 31;
    uint32_t sb = smem_u32(smem);

    if (tid == 0) { mbar_init(sb + 0, 1); mbar_init(sb + 8, 1); }
    if (warp == 0) tmalloc(sb + 16, 512);
    __syncthreads();
    uint32_t tmem;
    asm volatile("ld.shared.b32 %0, [%1];" : "=r"(tmem) : "r"(sb + 16));

    const __half* Asrc = UP ? g_xg : g_h;
    const __half* Ag = Asrc + (size_t)row0 * KTOT;
    const float*  Bg = W + (size_t)e * NOUT * KTOT + (size_t)n0 * KTOT;
    const uint32_t idesc = (1u << 4) | ((BN / 8) << 17) | ((BM / 16) << 24);

    const int SMA = 1024;
    const int SMB = 1024 + 2 * GM * 16384;

    auto CPA_A = [&](int s, int buf) {
        uint32_t aBase = sb + SMA + buf * (GM * 16384);
#pragma unroll
        for (int g = 0; g < GM; g++) {
            if (g < ng) {
                const __half* As = Ag + (size_t)g * BM * KTOT + s * 64;
                uint32_t dstb = aBase + g * 16384;
#pragma unroll
                for (int i = 0; i < 4; i++) {
                    int q = tid + i * 256;
                    int r = q >> 3, c = q & 7;
                    cpa16(dstb + SWZ((uint32_t)(r * 128 + c * 16)),
                          As + (size_t)r * KTOT + c * 8);
                }
            }
        }
        asm volatile("cp.async.commit_group;" ::: "memory");
    };
    float4 rB[8];
    auto LDG_B = [&](int s) {
        const float* Bs = Bg + s * 64;
#pragma unroll
        for (int i = 0; i < 8; i++) {
            int q = tid + i * 256;
            int rr = q >> 4, c4 = q & 15;
            rB[i] = *(const float4*)(Bs + (size_t)rr * KTOT + c4 * 4);
        }
    };
    auto STS_B = [&](int buf) {
        char* bb = smem + SMB + buf * 16384;
#pragma unroll
        for (int i = 0; i < 8; i++) {
            int q = tid + i * 256;
            int rr = q >> 4, c4 = q & 15;
            __half2 h0 = __floats2half2_rn(rB[i].x, rB[i].y);
            __half2 h1 = __floats2half2_rn(rB[i].z, rB[i].w);
            uint2 pk;
            pk.x = *(uint32_t*)&h0;
            pk.y = *(uint32_t*)&h1;
            uint32_t off = SWZ((uint32_t)(rr * 128 + (c4 >> 1) * 16)) + (c4 & 1) * 8;
            *(uint2*)(bb + off) = pk;
        }
    };

    uint32_t ph[2] = {0, 0};
    const int NKC = KTOT / 64;

    LDG_B(0);   // prologue: B(0) in flight before first iteration

    for (int s = 0; s < NKC; s++) {
        int buf = s & 1;
        if (s >= 2) { mbar_wait(sb + 8 * buf, ph[buf]); ph[buf] ^= 1; }
        CPA_A(s, buf);            // async A for stage s (buffer freed by the wait above)
        STS_B(buf);               // consume rB (loaded one iteration ago)
        if (s + 1 < NKC) LDG_B(s + 1);   // refill rB; latency spans rest of this iter + next-iter top
        asm volatile("cp.async.wait_group 0;" ::: "memory");
        asm volatile("fence.proxy.async.shared::cta;" ::: "memory");
        __syncthreads();

        if (warp == 0 && elect1()) {
            uint32_t aBase = sb + SMA + buf * (GM * 16384);
            uint64_t bd0 = mk_desc(sb + SMB + buf * 16384);
#pragma unroll
            for (int g = 0; g < GM; g++) {
                if (g < ng) {
                    uint64_t ad0 = mk_desc(aBase + g * 16384);
#pragma unroll
                    for (int ks = 0; ks < 4; ks++) {
                        mma_f16_ss(tmem + g * BN, ad0 + ks * 2, bd0 + ks * 2, idesc,
                                   (uint32_t)((s | ks) != 0));
                    }
                }
            }
            tccommit(sb + 8 * buf);
        }
    }
    mbar_wait(sb + 0, ph[0]);
    mbar_wait(sb + 8, ph[1]);
    asm volatile("tcgen05.fence::after_thread_sync;" ::: "memory");

    // ---- epilogue ----
    int sub = warp & 3;
    int hset = warp >> 2;
    const float* bp = bias + (size_t)e * NOUT + n0;
#pragma unroll
    for (int gg = 0; gg < 2; gg++) {
        int g = hset * 2 + gg;
        if (g >= ng) continue;
        int row = row0 + g * BM + sub * 32 + lane;
        bool ok = row < row_end;
#pragma unroll
        for (int cb = 0; cb < 4; cb++) {
            uint32_t r[32];
            ldtm32(r, tmem + g * BN + cb * 32);
            asm volatile("tcgen05.wait::ld.sync.aligned;" ::: "memory");
            if (ok) {
                int col = cb * 32;
                if (UP) {
                    __half2 o[16];
#pragma unroll
                    for (int j = 0; j < 16; j++) {
                        float v0 = __uint_as_float(r[2 * j])     + bp[col + 2 * j];
                        float v1 = __uint_as_float(r[2 * j + 1]) + bp[col + 2 * j + 1];
                        v0 = v0 / (1.f + __expf(-v0));
                        v1 = v1 / (1.f + __expf(-v1));
                        o[j] = __floats2half2_rn(v0, v1);
                    }
                    int4* dst = (int4*)(g_h + (size_t)row * HID + n0 + col);
#pragma unroll
                    for (int q = 0; q < 4; q++) dst[q] = ((int4*)o)[q];
                } else {
                    int tok = g_perm[row];
                    float4* dst = (float4*)(out + (size_t)tok * DIM + n0 + col);
#pragma unroll
                    for (int q = 0; q < 8; q++) {
                        float4 ov;
                        ov.x = __uint_as_float(r[4 * q + 0]) + bp[col + 4 * q + 0];
                        ov.y = __uint_as_float(r[4 * q + 1]) + bp[col + 4 * q + 1];
                        ov.z = __uint_as_float(r[4 * q + 2]) + bp[col + 4 * q + 2];
                        ov.w = __uint_as_float(r[4 * q + 3]) + bp[col + 4 * q + 3];
                        dst[q] = ov;
                    }
                }
            }
        }
    }
    __syncthreads();
    if (warp == 0) tmdealloc(tmem, 512);
#endif
}

// ================= wmma fallback GEMMs (active only in non-'a' image) =================
__global__ __launch_bounds__(256, 2) void k_up(const float* __restrict__ Wup,
                                               const float* __restrict__ bup) {
#if !TC5
    __shared__ __align__(128) char smem_raw[4 * BM * LDSMW * sizeof(__half)];
    __half (*sA)[BM][LDSMW] = (__half (*)[BM][LDSMW])smem_raw;
    __half (*sB)[BM][LDSMW] = (__half (*)[BM][LDSMW])(smem_raw + 2 * BM * LDSMW * sizeof(__half));
    float* stage_all = (float*)smem_raw;

    int mt = blockIdx.y;
    int e = g_tile_e[mt];
    if (e < 0) return;
    int row0 = g_tile_r0[mt], row_end = g_off[e + 1];
    int n0 = blockIdx.x * BN;
    int tid = threadIdx.x, warp = tid >> 5, lane = tid & 31;
    int wm = warp >> 2, wn = warp & 3;

    const __half* Ag = g_xg + (size_t)row0 * DIM;
    const float*  Bg = Wup + (size_t)e * HID * DIM + (size_t)n0 * DIM;

    wmma::fragment<wmma::accumulator, 16, 16, 16, float> c[4][2];
#pragma unroll
    for (int i = 0; i < 4; i++)
#pragma unroll
        for (int j = 0; j < 2; j++) wmma::fill_fragment(c[i][j], 0.f);

    int4 ra[2];
    float4 rb[4];

    auto LOADA = [&](int kt) {
#pragma unroll
        for (int i = 0; i < 2; i++) {
            int q = tid + i * 256, r = q >> 2, c8 = q & 3;
            ra[i] = *(const int4*)(Ag + (size_t)r * DIM + kt * BK + c8 * 8);
        }
    };
    auto LOADB = [&](int kt) {
#pragma unroll
        for (int i = 0; i < 4; i++) {
            int q = tid + i * 256, r = q >> 3, c4 = q & 7;
            rb[i] = *(const float4*)(Bg + (size_t)r * DIM + kt * BK + c4 * 4);
        }
    };
    auto STORE = [&](int buf) {
#pragma unroll
        for (int i = 0; i < 2; i++) {
            int q = tid + i * 256, r = q >> 2, c8 = q & 3;
            *(int4*)&sA[buf][r][c8 * 8] = ra[i];
        }
#pragma unroll
        for (int i = 0; i < 4; i++) {
            int q = tid + i * 256, r = q >> 3, c4 = q & 7;
            *(__half2*)&sB[buf][r][c4 * 4]     = __floats2half2_rn(rb[i].x, rb[i].y);
            *(__half2*)&sB[buf][r][c4 * 4 + 2] = __floats2half2_rn(rb[i].z, rb[i].w);
        }
    };
    auto COMP = [&](int buf) {
#pragma unroll
        for (int ks = 0; ks < 2; ks++) {
            wmma::fragment<wmma::matrix_a, 16, 16, 16, __half, wmma::row_major> a[4];
            wmma::fragment<wmma::matrix_b, 16, 16, 16, __half, wmma::col_major> b[2];
#pragma unroll
            for (int i = 0; i < 4; i++)
                wmma::load_matrix_sync(a[i], &sA[buf][wm * 64 + i * 16][ks * 16], LDSMW);
#pragma unroll
            for (int j = 0; j < 2; j++)
                wmma::load_matrix_sync(b[j], &sB[buf][wn * 32 + j * 16][ks * 16], LDSMW);
#pragma unroll
            for (int i = 0; i < 4; i++)
#pragma unroll
                for (int j = 0; j < 2; j++)
                    wmma::mma_sync(c[i][j], a[i], b[j], c[i][j]);
        }
    };

    LOADA(0); LOADB(0); STORE(0); __syncthreads();
    const int NK = DIM / BK;
    for (int kt = 1; kt < NK; kt++) {
        LOADA(kt); LOADB(kt);
        COMP((kt - 1) & 1);
        STORE(kt & 1);
        __syncthreads();
    }
    COMP((NK - 1) & 1);
    __syncthreads();

    float* st = stage_all + warp * 16 * 20;
#pragma unroll
    for (int i = 0; i < 4; i++)
#pragma unroll
        for (int j = 0; j < 2; j++) {
            wmma::store_matrix_sync(st, c[i][j], 20, wmma::mem_row_major);
            __syncwarp();
            int rr = lane >> 1, cbase = (lane & 1) * 8;
            int grow = row0 + wm * 64 + i * 16 + rr;
            if (grow < row_end) {
                int gcol = n0 + wn * 32 + j * 16 + cbase;
                __half2 o[4];
#pragma unroll
                for (int k2 = 0; k2 < 4; k2++) {
                    float v0 = st[rr * 20 + cbase + 2 * k2]     + bup[(size_t)e * HID + gcol + 2 * k2];
                    float v1 = st[rr * 20 + cbase + 2 * k2 + 1] + bup[(size_t)e * HID + gcol + 2 * k2 + 1];
                    v0 = v0 / (1.f + expf(-v0));
                    v1 = v1 / (1.f + expf(-v1));
                    o[k2] = __floats2half2_rn(v0, v1);
                }
                *(int4*)&g_h[(size_t)grow * HID + gcol] = *(int4*)o;
            }
            __syncwarp();
        }
#endif
}

__global__ __launch_bounds__(256, 2) void k_down(const float* __restrict__ Wdown,
                                                 const float* __restrict__ bdown,
                                                 float* __restrict__ out) {
#if !TC5
    __shared__ __align__(128) char smem_raw[4 * BM * LDSMW * sizeof(__half)];
    __half (*sA)[BM][LDSMW] = (__half (*)[BM][LDSMW])smem_raw;
    __half (*sB)[BM][LDSMW] = (__half (*)[BM][LDSMW])(smem_raw + 2 * BM * LDSMW * sizeof(__half));
    float* stage_all = (float*)smem_raw;

    int mt = blockIdx.y;
    int e = g_tile_e[mt];
    if (e < 0) return;
    int row0 = g_tile_r0[mt], row_end = g_off[e + 1];
    int n0 = blockIdx.x * BN;
    int tid = threadIdx.x, warp = tid >> 5, lane = tid & 31;
    int wm = warp >> 2, wn = warp & 3;

    const __half* Ag = g_h + (size_t)row0 * HID;
    const float*  Bg = Wdown + (size_t)e * DIM * HID + (size_t)n0 * HID;

    wmma::fragment<wmma::accumulator, 16, 16, 16, float> c[4][2];
#pragma unroll
    for (int i = 0; i < 4; i++)
#pragma unroll
        for (int j = 0; j < 2; j++) wmma::fill_fragment(c[i][j], 0.f);

    int4 ra[2];
    float4 rb[4];

    auto LOADA = [&](int kt) {
#pragma unroll
        for (int i = 0; i < 2; i++) {
            int q = tid + i * 256, r = q >> 2, c8 = q & 3;
            ra[i] = *(const int4*)(Ag + (size_t)r * HID + kt * BK + c8 * 8);
        }
    };
    auto LOADB = [&](int kt) {
#pragma unroll
        for (int i = 0; i < 4; i++) {
            int q = tid + i * 256, r = q >> 3, c4 = q & 7;
            rb[i] = *(const float4*)(Bg + (size_t)r * HID + kt * BK + c4 * 4);
        }
    };
    auto STORE = [&](int buf) {
#pragma unroll
        for (int i = 0; i < 2; i++) {
            int q = tid + i * 256, r = q >> 2, c8 = q & 3;
            *(int4*)&sA[buf][r][c8 * 8] = ra[i];
        }
#pragma unroll
        for (int i = 0; i < 4; i++) {
            int q = tid + i * 256, r = q >> 3, c4 = q & 7;
            *(__half2*)&sB[buf][r][c4 * 4]     = __floats2half2_rn(rb[i].x, rb[i].y);
            *(__half2*)&sB[buf][r][c4 * 4 + 2] = __floats2half2_rn(rb[i].z, rb[i].w);
        }
    };
    auto COMP = [&](int buf) {
#pragma unroll
        for (int ks = 0; ks < 2; ks++) {
            wmma::fragment<wmma::matrix_a, 16, 16, 16, __half, wmma::row_major> a[4];
            wmma::fragment<wmma::matrix_b, 16, 16, 16, __half, wmma::col_major> b[2];
#pragma unroll
            for (int i = 0; i < 4; i++)
                wmma::load_matrix_sync(a[i], &sA[buf][wm * 64 + i * 16][ks * 16], LDSMW);
#pragma unroll
            for (int j = 0; j < 2; j++)
                wmma::load_matrix_sync(b[j], &sB[buf][wn * 32 + j * 16][ks * 16], LDSMW);
#pragma unroll
            for (int i = 0; i < 4; i++)
#pragma unroll
                for (int j = 0; j < 2; j++)
                    wmma::mma_sync(c[i][j], a[i], b[j], c[i][j]);
        }
    };

    LOADA(0); LOADB(0); STORE(0); __syncthreads();
    const int NK = HID / BK;
    for (int kt = 1; kt < NK; kt++) {
        LOADA(kt); LOADB(kt);
        COMP((kt - 1) & 1);
        STORE(kt & 1);
        __syncthreads();
    }
    COMP((NK - 1) & 1);
    __syncthreads();

    float* st = stage_all + warp * 16 * 20;
#pragma unroll
    for (int i = 0; i < 4; i++)
#pragma unroll
        for (int j = 0; j < 2; j++) {
            wmma::store_matrix_sync(st, c[i][j], 20, wmma::mem_row_major);
            __syncwarp();
            int rr = lane >> 1, cbase = (lane & 1) * 8;
            int grow = row0 + wm * 64 + i * 16 + rr;
            if (grow < row_end) {
                int tok = g_perm[grow];
                int gcol = n0 + wn * 32 + j * 16 + cbase;
                float4 o0, o1;
                o0.x = st[rr * 20 + cbase + 0] + bdown[(size_t)e * DIM + gcol + 0];
                o0.y = st[rr * 20 + cbase + 1] + bdown[(size_t)e * DIM + gcol + 1];
                o0.z = st[rr * 20 + cbase + 2] + bdown[(size_t)e * DIM + gcol + 2];
                o0.w = st[rr * 20 + cbase + 3] + bdown[(size_t)e * DIM + gcol + 3];
                o1.x = st[rr * 20 + cbase + 4] + bdown[(size_t)e * DIM + gcol + 4];
                o1.y = st[rr * 20 + cbase + 5] + bdown[(size_t)e * DIM + gcol + 5];
                o1.z = st[rr * 20 + cbase + 6] + bdown[(size_t)e * DIM + gcol + 6];
                o1.w = st[rr * 20 + cbase + 7] + bdown[(size_t)e * DIM + gcol + 7];
                *(float4*)&out[(size_t)tok * DIM + gcol]     = o0;
                *(float4*)&out[(size_t)tok * DIM + gcol + 4] = o1;
            }
            __syncwarp();
        }
#endif
}

// ---------------- launcher ----------------
extern "C" void kernel_launch(void* const* d_in, const int* in_sizes, int n_in,
                              void* d_out, int out_size) {
    const float* x     = (const float*)d_in[0];
    const float* Wr    = (const float*)d_in[1];
    const float* br    = (const float*)d_in[2];
    const float* Wup   = (const float*)d_in[3];
    const float* bup   = (const float*)d_in[4];
    const float* Wdown = (const float*)d_in[5];
    const float* bdown = (const float*)d_in[6];
    float* out = (float*)d_out;

    cudaFuncSetAttribute(k_gemm<DIM, true>,  cudaFuncAttributeMaxDynamicSharedMemorySize, SMEM_BYTES);
    cudaFuncSetAttribute(k_gemm<HID, false>, cudaFuncAttributeMaxDynamicSharedMemorySize, SMEM_BYTES);

    k_init<<<1, 32>>>();
    k_router<<<NTOK / 8, 256>>>(x, Wr, br);
    k_scan<<<1, 1>>>();
    k_gather<<<NTOK / 8, 256>>>(x);
    k_up<<<dim3(HID / BN, MAXT), 256>>>(Wup, bup);                                      // empty in 'a'
    k_gemm<DIM, true ><<<dim3(HID / BN, MAXG), 256, SMEM_BYTES>>>(Wup, bup, nullptr);
    k_gemm<HID, false><<<dim3(DIM / BN, MAXG), 256, SMEM_BYTES>>>(Wdown, bdown, out);
    k_down<<<dim3(DIM / BN, MAXT), 256>>>(Wdown, bdown, out);                           // empty in 'a'
}

// round 8
// speedup vs baseline: 1.8305x; 1.3728x over previous
#include <cuda_runtime.h>
#include <cuda_fp16.h>
#include <mma.h>
#include <stdint.h>
#include <math.h>

using namespace nvcuda;

#define NTOK 8192
#define DIM  1024
#define HID  4096
#define NE   8
#define BM   128
#define BN   128
#define BK   32
#define LDSMW (BK + 8)
#define GM   4
#define KC   32                         // K per stage
#define STG  5                          // smem stage buffers (lookahead 3 -> 2-iter MMA slack)
#define A_ST (GM * BM * KC * 2)         // 32768
#define B_ST (BN * KC * 2)              // 8192
#define STAGE_BYTES (A_ST + B_ST)       // 40960
#define PAD  (GM*BM)
#define MAXG 24
#define MAXT (NTOK / BM + NE)
#define SMEM_BYTES (1024 + 1024 + STG * STAGE_BYTES)   // 206848

#if defined(__CUDA_ARCH_FEAT_SM103_ALL) || defined(__CUDA_ARCH_FEAT_SM100_ALL) || defined(__CUDA_ARCH_FEAT_SM101_ALL)
#define TC5 1
#else
#define TC5 0
#endif

// ---------------- device scratch ----------------
__device__ int    g_expert[NTOK];
__device__ int    g_count[NE];
__device__ int    g_cursor[NE];
__device__ int    g_off[NE + 1];
__device__ int    g_perm[NTOK];
__device__ int    g_grp_e[MAXG];
__device__ int    g_grp_r0[MAXG];
__device__ int    g_grp_ng[MAXG];
__device__ int    g_tile_e[MAXT];
__device__ int    g_tile_r0[MAXT];
__device__ __half g_xg[(size_t)(NTOK + PAD) * DIM];
__device__ __half g_h [(size_t)(NTOK + PAD) * HID];
__device__ __half g_wup[(size_t)NE * HID * DIM];    // fp16 weights (pre-converted)
__device__ __half g_wdn[(size_t)NE * DIM * HID];

// ---------------- PTX helpers ----------------
__device__ __forceinline__ uint32_t smem_u32(const void* p) {
    uint32_t a;
    asm("{ .reg .u64 t; cvta.to.shared.u64 t, %1; cvt.u32.u64 %0, t; }" : "=r"(a) : "l"(p));
    return a;
}
#if TC5
__device__ __forceinline__ bool elect1() {
    uint32_t r;
    asm volatile("{\n\t.reg .pred p;\n\telect.sync _|p, 0xFFFFFFFF;\n\tselp.b32 %0,1,0,p;\n\t}" : "=r"(r));
    return r != 0;
}
__device__ __forceinline__ void mbar_init(uint32_t a, uint32_t cnt) {
    asm volatile("mbarrier.init.shared.b64 [%0], %1;" :: "r"(a), "r"(cnt) : "memory");
}
__device__ __forceinline__ void mbar_wait(uint32_t a, uint32_t ph) {
    asm volatile(
        "{\n\t.reg .pred P;\n\t"
        "LW_%=:\n\t"
        "mbarrier.try_wait.parity.acquire.cta.shared::cta.b64 P, [%0], %1, 0x989680;\n\t"
        "@P bra LD_%=;\n\t"
        "bra LW_%=;\n\t"
        "LD_%=:\n\t}"
        :: "r"(a), "r"(ph) : "memory");
}
__device__ __forceinline__ void tmalloc(uint32_t smem_dst, uint32_t ncols) {
    asm volatile("tcgen05.alloc.cta_group::1.sync.aligned.shared::cta.b32 [%0], %1;"
                 :: "r"(smem_dst), "r"(ncols) : "memory");
}
__device__ __forceinline__ void tmdealloc(uint32_t tmem, uint32_t ncols) {
    asm volatile("tcgen05.relinquish_alloc_permit.cta_group::1.sync.aligned;");
    asm volatile("tcgen05.dealloc.cta_group::1.sync.aligned.b32 %0, %1;" :: "r"(tmem), "r"(ncols));
}
__device__ __forceinline__ void mma_f16_ss(uint32_t d, uint64_t ad, uint64_t bd, uint32_t idesc, uint32_t en) {
    asm volatile(
        "{\n\t.reg .pred p;\n\tsetp.ne.u32 p, %5, 0;\n\t"
        "tcgen05.mma.cta_group::1.kind::f16 [%0], %1, %2, %3, {%4,%4,%4,%4}, p;\n\t}"
        :: "r"(d), "l"(ad), "l"(bd), "r"(idesc), "r"(0u), "r"(en) : "memory");
}
__device__ __forceinline__ void tccommit(uint32_t mbar) {
    asm volatile("tcgen05.commit.cta_group::1.mbarrier::arrive::one.shared::cluster.b64 [%0];"
                 :: "r"(mbar) : "memory");
}
__device__ __forceinline__ void cpa16(uint32_t dst, const void* src) {
    asm volatile("cp.async.cg.shared.global [%0], [%1], 16;" :: "r"(dst), "l"(src) : "memory");
}
__device__ __forceinline__ void ldtm32(uint32_t* r, uint32_t addr) {
    asm volatile(
        "tcgen05.ld.sync.aligned.32x32b.x32.b32 "
        "{%0, %1, %2, %3, %4, %5, %6, %7, "
        " %8, %9, %10, %11, %12, %13, %14, %15, "
        " %16, %17, %18, %19, %20, %21, %22, %23, "
        " %24, %25, %26, %27, %28, %29, %30, %31}, [%32];"
        : "=r"(r[0]),  "=r"(r[1]),  "=r"(r[2]),  "=r"(r[3]),
          "=r"(r[4]),  "=r"(r[5]),  "=r"(r[6]),  "=r"(r[7]),
          "=r"(r[8]),  "=r"(r[9]),  "=r"(r[10]), "=r"(r[11]),
          "=r"(r[12]), "=r"(r[13]), "=r"(r[14]), "=r"(r[15]),
          "=r"(r[16]), "=r"(r[17]), "=r"(r[18]), "=r"(r[19]),
          "=r"(r[20]), "=r"(r[21]), "=r"(r[22]), "=r"(r[23]),
          "=r"(r[24]), "=r"(r[25]), "=r"(r[26]), "=r"(r[27]),
          "=r"(r[28]), "=r"(r[29]), "=r"(r[30]), "=r"(r[31])
        : "r"(addr));
}
#endif
#define SWZ(o)   ((o) ^ (((o) >> 3) & 0x70))
#define SWZ64(o) ((o) ^ (((o) >> 3) & 0x30))
// SW64 K-major descriptor: layout=4, SBO=32 (512B = 8 rows x 64B), LBO=1 (16B)
__device__ __forceinline__ uint64_t mk_desc64(uint32_t addr) {
    return ((uint64_t)4 << 61) | ((uint64_t)1 << 46) | ((uint64_t)32 << 32) |
           ((uint64_t)1 << 16) | ((addr >> 4) & 0x3FFF);
}

// ---------------- weight fp32 -> fp16 convert ----------------
__global__ void k_convert(const float* __restrict__ Wup, const float* __restrict__ Wdown) {
    const size_t HALF = (size_t)NE * HID * DIM;       // 33.5M, divisible by 2048
    size_t base = ((size_t)blockIdx.x * 256 + threadIdx.x) * 8;
    const float* src;
    __half* dst;
    size_t off;
    if (base < HALF) { src = Wup;   dst = g_wup; off = base; }
    else             { src = Wdown; dst = g_wdn; off = base - HALF; }
    float4 v0 = *(const float4*)(src + off);
    float4 v1 = *(const float4*)(src + off + 4);
    __half2 h[4];
    h[0] = __floats2half2_rn(v0.x, v0.y);
    h[1] = __floats2half2_rn(v0.z, v0.w);
    h[2] = __floats2half2_rn(v1.x, v1.y);
    h[3] = __floats2half2_rn(v1.z, v1.w);
    *(int4*)(dst + off) = *(int4*)h;
}

// ---------------- init ----------------
__global__ void k_init() {
    int i = threadIdx.x;
    if (i < NE) { g_count[i] = 0; g_cursor[i] = 0; }
}

// ---------------- router ----------------
__global__ void k_router(const float* __restrict__ x,
                         const float* __restrict__ Wr,
                         const float* __restrict__ br) {
    __shared__ float sW[NE * DIM];
    for (int i = threadIdx.x; i < NE * DIM; i += 256) sW[i] = Wr[i];
    __syncthreads();

    int warp = threadIdx.x >> 5, lane = threadIdx.x & 31;
    int t = blockIdx.x * 8 + warp;
    const float4* xr = (const float4*)(x + (size_t)t * DIM);

    float acc[NE];
#pragma unroll
    for (int e = 0; e < NE; e++) acc[e] = 0.f;
#pragma unroll
    for (int p = 0; p < 8; p++) {
        float4 v = xr[p * 32 + lane];
        int c = (p * 32 + lane) * 4;
#pragma unroll
        for (int e = 0; e < NE; e++) {
            const float* w = &sW[e * DIM + c];
            acc[e] += v.x * w[0] + v.y * w[1] + v.z * w[2] + v.w * w[3];
        }
    }
#pragma unroll
    for (int e = 0; e < NE; e++)
#pragma unroll
        for (int o = 16; o; o >>= 1) acc[e] += __shfl_xor_sync(0xffffffffu, acc[e], o);

    if (lane == 0) {
        int best = 0;
        float bv = acc[0] + br[0];
#pragma unroll
        for (int e = 1; e < NE; e++) {
            float v = acc[e] + br[e];
            if (v > bv) { bv = v; best = e; }
        }
        g_expert[t] = best;
        atomicAdd(&g_count[best], 1);
    }
}

// ---------------- scan ----------------
__global__ void k_scan() {
    if (threadIdx.x != 0) return;
    int o = 0;
    for (int e = 0; e < NE; e++) { g_off[e] = o; o += g_count[e]; }
    g_off[NE] = o;
    int t = 0;
    for (int e = 0; e < NE; e++) {
        int tiles = (g_count[e] + BM - 1) / BM;
        for (int m = 0; m < tiles; m += GM) {
            g_grp_e[t] = e;
            g_grp_r0[t] = g_off[e] + m * BM;
            int rem = tiles - m;
            g_grp_ng[t] = rem < GM ? rem : GM;
            t++;
        }
    }
    for (; t < MAXG; t++) g_grp_e[t] = -1;
    int tt = 0;
    for (int e = 0; e < NE; e++) {
        int tiles = (g_count[e] + BM - 1) / BM;
        for (int m = 0; m < tiles; m++) { g_tile_e[tt] = e; g_tile_r0[tt] = g_off[e] + m * BM; tt++; }
    }
    for (; tt < MAXT; tt++) g_tile_e[tt] = -1;
}

// ---------------- gather + fp32->fp16 ----------------
__global__ void k_gather(const float* __restrict__ x) {
    int gw = (blockIdx.x * blockDim.x + threadIdx.x) >> 5;
    int lane = threadIdx.x & 31;
    if (gw >= NTOK) return;
    int t = gw, e = g_expert[t];
    int slot = 0;
    if (lane == 0) {
        int r = atomicAdd(&g_cursor[e], 1);
        slot = g_off[e] + r;
        g_perm[slot] = t;
    }
    slot = __shfl_sync(0xffffffffu, slot, 0);
    const float4* src = (const float4*)(x + (size_t)t * DIM);
    __half2* dst = (__half2*)(g_xg + (size_t)slot * DIM);
#pragma unroll
    for (int p = 0; p < 8; p++) {
        float4 v = src[p * 32 + lane];
        dst[(p * 32 + lane) * 2]     = __floats2half2_rn(v.x, v.y);
        dst[(p * 32 + lane) * 2 + 1] = __floats2half2_rn(v.z, v.w);
    }
}

// ================= tcgen05 grouped GEMM: 5-buffer / lookahead-3 cp.async pipeline =================
template<int KTOT, bool UP>
__global__ void __launch_bounds__(256, 1) k_gemm(const float* __restrict__ Wunused,
                                                 const float* __restrict__ bias,
                                                 float* __restrict__ out) {
#if TC5
    extern __shared__ char smem_raw[];
    char* smem = (char*)(((uintptr_t)smem_raw + 1023) & ~(uintptr_t)1023);
    const int NOUT = UP ? HID : DIM;

    int gi = blockIdx.y;
    int e = g_grp_e[gi];
    if (e < 0) return;
    int row0 = g_grp_r0[gi], ng = g_grp_ng[gi], row_end = g_off[e + 1];
    int n0 = blockIdx.x * BN;
    int tid = threadIdx.x, warp = tid >> 5, lane = tid & 31;
    uint32_t sb = smem_u32(smem);

    if (tid == 0) {
#pragma unroll
        for (int j = 0; j < STG; j++) mbar_init(sb + 8 * j, 1);
    }
    if (warp == 0) tmalloc(sb + 64, 512);
    __syncthreads();
    uint32_t tmem;
    asm volatile("ld.shared.b32 %0, [%1];" : "=r"(tmem) : "r"(sb + 64));

    const __half* Asrc = UP ? g_xg : g_h;
    const __half* Ag = Asrc + (size_t)row0 * KTOT;
    const __half* Bg = (UP ? g_wup : g_wdn) + (size_t)e * NOUT * KTOT + (size_t)n0 * KTOT;
    const uint32_t idesc = (1u << 4) | ((BN / 8) << 17) | ((BM / 16) << 24);
    const int SMA = 1024;

    auto LOAD = [&](int s, int buf) {
        uint32_t stBase = sb + SMA + buf * STAGE_BYTES;
#pragma unroll
        for (int g = 0; g < GM; g++) {
            if (g < ng) {
                const __half* As = Ag + (size_t)g * BM * KTOT + s * KC;
                uint32_t ab = stBase + g * 8192;
#pragma unroll
                for (int i = 0; i < 2; i++) {
                    int q = tid + i * 256;
                    int r = q >> 2, c = q & 3;
                    cpa16(ab + SWZ64((uint32_t)(r * 64 + c * 16)),
                          As + (size_t)r * KTOT + c * 8);
                }
            }
        }
        const __half* Bs = Bg + s * KC;
        uint32_t bb = stBase + A_ST;
#pragma unroll
        for (int i = 0; i < 2; i++) {
            int q = tid + i * 256;
            int r = q >> 2, c = q & 3;
            cpa16(bb + SWZ64((uint32_t)(r * 64 + c * 16)),
                  Bs + (size_t)r * KTOT + c * 8);
        }
    };

    const int NKC = KTOT / KC;           // UP: 32, DOWN: 128

    // prologue: stages 0..2 in flight (3 groups)
#pragma unroll
    for (int p = 0; p < 3; p++) { LOAD(p, p); asm volatile("cp.async.commit_group;" ::: "memory"); }

    for (int s = 0; s < NKC; s++) {
        // free buffer (s+3)%STG previously held stage s-2 -> wait its MMA (2-iter slack)
        if (s >= 2) mbar_wait(sb + 8 * ((s - 2) % STG), (uint32_t)(((s - 2) / STG) & 1));
        if (s + 3 < NKC) LOAD(s + 3, (s + 3) % STG);
        asm volatile("cp.async.commit_group;" ::: "memory");   // (possibly empty) keeps count exact
        asm volatile("cp.async.wait_group 3;" ::: "memory");   // stage s arrived (<=3 newer pending)
        asm volatile("fence.proxy.async.shared::cta;" ::: "memory");
        __syncthreads();

        if (warp == 0 && elect1()) {
            uint32_t stBase = sb + SMA + (s % STG) * STAGE_BYTES;
            uint64_t bd = mk_desc64(stBase + A_ST);
#pragma unroll
            for (int g = 0; g < GM; g++) {
                if (g < ng) {
                    uint64_t ad = mk_desc64(stBase + g * 8192);
#pragma unroll
                    for (int ks = 0; ks < 2; ks++) {
                        mma_f16_ss(tmem + g * BN, ad + ks * 2, bd + ks * 2, idesc,
                                   (uint32_t)((s | ks) != 0));
                    }
                }
            }
            tccommit(sb + 8 * (s % STG));
        }
    }
    // drain: wait last commit on every slot
#pragma unroll
    for (int j = 0; j < STG; j++) {
        int sj = (NKC - 1) - ((NKC - 1 - j) % STG);   // last s<NKC with s%STG==j (NKC>=STG)
        mbar_wait(sb + 8 * j, (uint32_t)((sj / STG) & 1));
    }
    asm volatile("tcgen05.fence::after_thread_sync;" ::: "memory");

    // ---- epilogue ----
    int sub = warp & 3;
    int hset = warp >> 2;
    const float* bp = bias + (size_t)e * NOUT + n0;
#pragma unroll
    for (int gg = 0; gg < 2; gg++) {
        int g = hset * 2 + gg;
        if (g >= ng) continue;
        int row = row0 + g * BM + sub * 32 + lane;
        bool ok = row < row_end;
#pragma unroll
        for (int cb = 0; cb < 4; cb++) {
            uint32_t r[32];
            ldtm32(r, tmem + g * BN + cb * 32);
            asm volatile("tcgen05.wait::ld.sync.aligned;" ::: "memory");
            if (ok) {
                int col = cb * 32;
                if (UP) {
                    __half2 o[16];
#pragma unroll
                    for (int j = 0; j < 16; j++) {
                        float v0 = __uint_as_float(r[2 * j])     + bp[col + 2 * j];
                        float v1 = __uint_as_float(r[2 * j + 1]) + bp[col + 2 * j + 1];
                        v0 = v0 / (1.f + __expf(-v0));
                        v1 = v1 / (1.f + __expf(-v1));
                        o[j] = __floats2half2_rn(v0, v1);
                    }
                    int4* dst = (int4*)(g_h + (size_t)row * HID + n0 + col);
#pragma unroll
                    for (int q = 0; q < 4; q++) dst[q] = ((int4*)o)[q];
                } else {
                    int tok = g_perm[row];
                    float4* dst = (float4*)(out + (size_t)tok * DIM + n0 + col);
#pragma unroll
                    for (int q = 0; q < 8; q++) {
                        float4 ov;
                        ov.x = __uint_as_float(r[4 * q + 0]) + bp[col + 4 * q + 0];
                        ov.y = __uint_as_float(r[4 * q + 1]) + bp[col + 4 * q + 1];
                        ov.z = __uint_as_float(r[4 * q + 2]) + bp[col + 4 * q + 2];
                        ov.w = __uint_as_float(r[4 * q + 3]) + bp[col + 4 * q + 3];
                        dst[q] = ov;
                    }
                }
            }
        }
    }
    __syncthreads();
    if (warp == 0) tmdealloc(tmem, 512);
#endif
}

// ================= wmma fallback GEMMs (active only in non-'a' image) =================
__global__ __launch_bounds__(256, 2) void k_up(const float* __restrict__ Wup,
                                               const float* __restrict__ bup) {
#if !TC5
    __shared__ __align__(128) char smem_raw[4 * BM * LDSMW * sizeof(__half)];
    __half (*sA)[BM][LDSMW] = (__half (*)[BM][LDSMW])smem_raw;
    __half (*sB)[BM][LDSMW] = (__half (*)[BM][LDSMW])(smem_raw + 2 * BM * LDSMW * sizeof(__half));
    float* stage_all = (float*)smem_raw;

    int mt = blockIdx.y;
    int e = g_tile_e[mt];
    if (e < 0) return;
    int row0 = g_tile_r0[mt], row_end = g_off[e + 1];
    int n0 = blockIdx.x * BN;
    int tid = threadIdx.x, warp = tid >> 5, lane = tid & 31;
    int wm = warp >> 2, wn = warp & 3;

    const __half* Ag = g_xg + (size_t)row0 * DIM;
    const float*  Bg = Wup + (size_t)e * HID * DIM + (size_t)n0 * DIM;

    wmma::fragment<wmma::accumulator, 16, 16, 16, float> c[4][2];
#pragma unroll
    for (int i = 0; i < 4; i++)
#pragma unroll
        for (int j = 0; j < 2; j++) wmma::fill_fragment(c[i][j], 0.f);

    int4 ra[2];
    float4 rb[4];

    auto LOADA = [&](int kt) {
#pragma unroll
        for (int i = 0; i < 2; i++) {
            int q = tid + i * 256, r = q >> 2, c8 = q & 3;
            ra[i] = *(const int4*)(Ag + (size_t)r * DIM + kt * BK + c8 * 8);
        }
    };
    auto LOADB = [&](int kt) {
#pragma unroll
        for (int i = 0; i < 4; i++) {
            int q = tid + i * 256, r = q >> 3, c4 = q & 7;
            rb[i] = *(const float4*)(Bg + (size_t)r * DIM + kt * BK + c4 * 4);
        }
    };
    auto STORE = [&](int buf) {
#pragma unroll
        for (int i = 0; i < 2; i++) {
            int q = tid + i * 256, r = q >> 2, c8 = q & 3;
            *(int4*)&sA[buf][r][c8 * 8] = ra[i];
        }
#pragma unroll
        for (int i = 0; i < 4; i++) {
            int q = tid + i * 256, r = q >> 3, c4 = q & 7;
            *(__half2*)&sB[buf][r][c4 * 4]     = __floats2half2_rn(rb[i].x, rb[i].y);
            *(__half2*)&sB[buf][r][c4 * 4 + 2] = __floats2half2_rn(rb[i].z, rb[i].w);
        }
    };
    auto COMP = [&](int buf) {
#pragma unroll
        for (int ks = 0; ks < 2; ks++) {
            wmma::fragment<wmma::matrix_a, 16, 16, 16, __half, wmma::row_major> a[4];
            wmma::fragment<wmma::matrix_b, 16, 16, 16, __half, wmma::col_major> b[2];
#pragma unroll
            for (int i = 0; i < 4; i++)
                wmma::load_matrix_sync(a[i], &sA[buf][wm * 64 + i * 16][ks * 16], LDSMW);
#pragma unroll
            for (int j = 0; j < 2; j++)
                wmma::load_matrix_sync(b[j], &sB[buf][wn * 32 + j * 16][ks * 16], LDSMW);
#pragma unroll
            for (int i = 0; i < 4; i++)
#pragma unroll
                for (int j = 0; j < 2; j++)
                    wmma::mma_sync(c[i][j], a[i], b[j], c[i][j]);
        }
    };

    LOADA(0); LOADB(0); STORE(0); __syncthreads();
    const int NK = DIM / BK;
    for (int kt = 1; kt < NK; kt++) {
        LOADA(kt); LOADB(kt);
        COMP((kt - 1) & 1);
        STORE(kt & 1);
        __syncthreads();
    }
    COMP((NK - 1) & 1);
    __syncthreads();

    float* st = stage_all + warp * 16 * 20;
#pragma unroll
    for (int i = 0; i < 4; i++)
#pragma unroll
        for (int j = 0; j < 2; j++) {
            wmma::store_matrix_sync(st, c[i][j], 20, wmma::mem_row_major);
            __syncwarp();
            int rr = lane >> 1, cbase = (lane & 1) * 8;
            int grow = row0 + wm * 64 + i * 16 + rr;
            if (grow < row_end) {
                int gcol = n0 + wn * 32 + j * 16 + cbase;
                __half2 o[4];
#pragma unroll
                for (int k2 = 0; k2 < 4; k2++) {
                    float v0 = st[rr * 20 + cbase + 2 * k2]     + bup[(size_t)e * HID + gcol + 2 * k2];
                    float v1 = st[rr * 20 + cbase + 2 * k2 + 1] + bup[(size_t)e * HID + gcol + 2 * k2 + 1];
                    v0 = v0 / (1.f + expf(-v0));
                    v1 = v1 / (1.f + expf(-v1));
                    o[k2] = __floats2half2_rn(v0, v1);
                }
                *(int4*)&g_h[(size_t)grow * HID + gcol] = *(int4*)o;
            }
            __syncwarp();
        }
#endif
}

__global__ __launch_bounds__(256, 2) void k_down(const float* __restrict__ Wdown,
                                                 const float* __restrict__ bdown,
                                                 float* __restrict__ out) {
#if !TC5
    __shared__ __align__(128) char smem_raw[4 * BM * LDSMW * sizeof(__half)];
    __half (*sA)[BM][LDSMW] = (__half (*)[BM][LDSMW])smem_raw;
    __half (*sB)[BM][LDSMW] = (__half (*)[BM][LDSMW])(smem_raw + 2 * BM * LDSMW * sizeof(__half));
    float* stage_all = (float*)smem_raw;

    int mt = blockIdx.y;
    int e = g_tile_e[mt];
    if (e < 0) return;
    int row0 = g_tile_r0[mt], row_end = g_off[e + 1];
    int n0 = blockIdx.x * BN;
    int tid = threadIdx.x, warp = tid >> 5, lane = tid & 31;
    int wm = warp >> 2, wn = warp & 3;

    const __half* Ag = g_h + (size_t)row0 * HID;
    const float*  Bg = Wdown + (size_t)e * DIM * HID + (size_t)n0 * HID;

    wmma::fragment<wmma::accumulator, 16, 16, 16, float> c[4][2];
#pragma unroll
    for (int i = 0; i < 4; i++)
#pragma unroll
        for (int j = 0; j < 2; j++) wmma::fill_fragment(c[i][j], 0.f);

    int4 ra[2];
    float4 rb[4];

    auto LOADA = [&](int kt) {
#pragma unroll
        for (int i = 0; i < 2; i++) {
            int q = tid + i * 256, r = q >> 2, c8 = q & 3;
            ra[i] = *(const int4*)(Ag + (size_t)r * HID + kt * BK + c8 * 8);
        }
    };
    auto LOADB = [&](int kt) {
#pragma unroll
        for (int i = 0; i < 4; i++) {
            int q = tid + i * 256, r = q >> 3, c4 = q & 7;
            rb[i] = *(const float4*)(Bg + (size_t)r * HID + kt * BK + c4 * 4);
        }
    };
    auto STORE = [&](int buf) {
#pragma unroll
        for (int i = 0; i < 2; i++) {
            int q = tid + i * 256, r = q >> 2, c8 = q & 3;
            *(int4*)&sA[buf][r][c8 * 8] = ra[i];
        }
#pragma unroll
        for (int i = 0; i < 4; i++) {
            int q = tid + i * 256, r = q >> 3, c4 = q & 7;
            *(__half2*)&sB[buf][r][c4 * 4]     = __floats2half2_rn(rb[i].x, rb[i].y);
            *(__half2*)&sB[buf][r][c4 * 4 + 2] = __floats2half2_rn(rb[i].z, rb[i].w);
        }
    };
    auto COMP = [&](int buf) {
#pragma unroll
        for (int ks = 0; ks < 2; ks++) {
            wmma::fragment<wmma::matrix_a, 16, 16, 16, __half, wmma::row_major> a[4];
            wmma::fragment<wmma::matrix_b, 16, 16, 16, __half, wmma::col_major> b[2];
#pragma unroll
            for (int i = 0; i < 4; i++)
                wmma::load_matrix_sync(a[i], &sA[buf][wm * 64 + i * 16][ks * 16], LDSMW);
#pragma unroll
            for (int j = 0; j < 2; j++)
                wmma::load_matrix_sync(b[j], &sB[buf][wn * 32 + j * 16][ks * 16], LDSMW);
#pragma unroll
            for (int i = 0; i < 4; i++)
#pragma unroll
                for (int j = 0; j < 2; j++)
                    wmma::mma_sync(c[i][j], a[i], b[j], c[i][j]);
        }
    };

    LOADA(0); LOADB(0); STORE(0); __syncthreads();
    const int NK = HID / BK;
    for (int kt = 1; kt < NK; kt++) {
        LOADA(kt); LOADB(kt);
        COMP((kt - 1) & 1);
        STORE(kt & 1);
        __syncthreads();
    }
    COMP((NK - 1) & 1);
    __syncthreads();

    float* st = stage_all + warp * 16 * 20;
#pragma unroll
    for (int i = 0; i < 4; i++)
#pragma unroll
        for (int j = 0; j < 2; j++) {
            wmma::store_matrix_sync(st, c[i][j], 20, wmma::mem_row_major);
            __syncwarp();
            int rr = lane >> 1, cbase = (lane & 1) * 8;
            int grow = row0 + wm * 64 + i * 16 + rr;
            if (grow < row_end) {
                int tok = g_perm[grow];
                int gcol = n0 + wn * 32 + j * 16 + cbase;
                float4 o0, o1;
                o0.x = st[rr * 20 + cbase + 0] + bdown[(size_t)e * DIM + gcol + 0];
                o0.y = st[rr * 20 + cbase + 1] + bdown[(size_t)e * DIM + gcol + 1];
                o0.z = st[rr * 20 + cbase + 2] + bdown[(size_t)e * DIM + gcol + 2];
                o0.w = st[rr * 20 + cbase + 3] + bdown[(size_t)e * DIM + gcol + 3];
                o1.x = st[rr * 20 + cbase + 4] + bdown[(size_t)e * DIM + gcol + 4];
                o1.y = st[rr * 20 + cbase + 5] + bdown[(size_t)e * DIM + gcol + 5];
                o1.z = st[rr * 20 + cbase + 6] + bdown[(size_t)e * DIM + gcol + 6];
                o1.w = st[rr * 20 + cbase + 7] + bdown[(size_t)e * DIM + gcol + 7];
                *(float4*)&out[(size_t)tok * DIM + gcol]     = o0;
                *(float4*)&out[(size_t)tok * DIM + gcol + 4] = o1;
            }
            __syncwarp();
        }
#endif
}

// ---------------- launcher ----------------
extern "C" void kernel_launch(void* const* d_in, const int* in_sizes, int n_in,
                              void* d_out, int out_size) {
    const float* x     = (const float*)d_in[0];
    const float* Wr    = (const float*)d_in[1];
    const float* br    = (const float*)d_in[2];
    const float* Wup   = (const float*)d_in[3];
    const float* bup   = (const float*)d_in[4];
    const float* Wdown = (const float*)d_in[5];
    const float* bdown = (const float*)d_in[6];
    float* out = (float*)d_out;

    cudaFuncSetAttribute(k_gemm<DIM, true>,  cudaFuncAttributeMaxDynamicSharedMemorySize, SMEM_BYTES);
    cudaFuncSetAttribute(k_gemm<HID, false>, cudaFuncAttributeMaxDynamicSharedMemorySize, SMEM_BYTES);

    const size_t TOTW = 2 * (size_t)NE * HID * DIM;      // 67.1M elements
    k_convert<<<(int)(TOTW / 2048), 256>>>(Wup, Wdown);
    k_init<<<1, 32>>>();
    k_router<<<NTOK / 8, 256>>>(x, Wr, br);
    k_scan<<<1, 1>>>();
    k_gather<<<NTOK / 8, 256>>>(x);
    k_up<<<dim3(HID / BN, MAXT), 256>>>(Wup, bup);                                      // empty in 'a'
    k_gemm<DIM, true ><<<dim3(HID / BN, MAXG), 256, SMEM_BYTES>>>(Wup, bup, nullptr);
    k_gemm<HID, false><<<dim3(DIM / BN, MAXG), 256, SMEM_BYTES>>>(Wdown, bdown, out);
    k_down<<<dim3(DIM / BN, MAXT), 256>>>(Wdown, bdown, out);                           // empty in 'a'
}

// round 9
// speedup vs baseline: 2.2021x; 1.2030x over previous
#include <cuda_runtime.h>
#include <cuda_fp16.h>
#include <mma.h>
#include <stdint.h>
#include <math.h>

using namespace nvcuda;

#define NTOK 8192
#define DIM  1024
#define HID  4096
#define NE   8
#define BM   128
#define BN   256                        // wide N tile (TMEM: GM*BN = 512 cols)
#define GM   2
#define BNW  128                        // wmma fallback N tile
#define BK   32
#define LDSMW (BK + 8)
#define KC   32
#define STG  5
#define A_ST (GM * BM * KC * 2)         // 16384
#define B_ST (BN * KC * 2)              // 16384
#define STAGE_BYTES (A_ST + B_ST)       // 32768
#define PAD  (GM*BM)
#define MAXG (NTOK / BM / GM + NE)      // 40
#define MAXT (NTOK / BM + NE)
#define SMEM_BYTES (1024 + 1024 + STG * STAGE_BYTES)   // 165888

#if defined(__CUDA_ARCH_FEAT_SM103_ALL) || defined(__CUDA_ARCH_FEAT_SM100_ALL) || defined(__CUDA_ARCH_FEAT_SM101_ALL)
#define TC5 1
#else
#define TC5 0
#endif

// ---------------- device scratch ----------------
__device__ int    g_expert[NTOK];
__device__ int    g_count[NE];
__device__ int    g_cursor[NE];
__device__ int    g_off[NE + 1];
__device__ int    g_perm[NTOK];
__device__ int    g_grp_e[MAXG];
__device__ int    g_grp_r0[MAXG];
__device__ int    g_grp_ng[MAXG];
__device__ int    g_tile_e[MAXT];
__device__ int    g_tile_r0[MAXT];
__device__ __half g_xg[(size_t)(NTOK + PAD) * DIM];
__device__ __half g_h [(size_t)(NTOK + PAD) * HID];
__device__ __half g_wup[(size_t)NE * HID * DIM];
__device__ __half g_wdn[(size_t)NE * DIM * HID];

// ---------------- PTX helpers ----------------
__device__ __forceinline__ uint32_t smem_u32(const void* p) {
    uint32_t a;
    asm("{ .reg .u64 t; cvta.to.shared.u64 t, %1; cvt.u32.u64 %0, t; }" : "=r"(a) : "l"(p));
    return a;
}
#if TC5
__device__ __forceinline__ bool elect1() {
    uint32_t r;
    asm volatile("{\n\t.reg .pred p;\n\telect.sync _|p, 0xFFFFFFFF;\n\tselp.b32 %0,1,0,p;\n\t}" : "=r"(r));
    return r != 0;
}
__device__ __forceinline__ void mbar_init(uint32_t a, uint32_t cnt) {
    asm volatile("mbarrier.init.shared.b64 [%0], %1;" :: "r"(a), "r"(cnt) : "memory");
}
__device__ __forceinline__ void mbar_wait(uint32_t a, uint32_t ph) {
    asm volatile(
        "{\n\t.reg .pred P;\n\t"
        "LW_%=:\n\t"
        "mbarrier.try_wait.parity.acquire.cta.shared::cta.b64 P, [%0], %1, 0x989680;\n\t"
        "@P bra LD_%=;\n\t"
        "bra LW_%=;\n\t"
        "LD_%=:\n\t}"
        :: "r"(a), "r"(ph) : "memory");
}
__device__ __forceinline__ void tmalloc(uint32_t smem_dst, uint32_t ncols) {
    asm volatile("tcgen05.alloc.cta_group::1.sync.aligned.shared::cta.b32 [%0], %1;"
                 :: "r"(smem_dst), "r"(ncols) : "memory");
}
__device__ __forceinline__ void tmdealloc(uint32_t tmem, uint32_t ncols) {
    asm volatile("tcgen05.relinquish_alloc_permit.cta_group::1.sync.aligned;");
    asm volatile("tcgen05.dealloc.cta_group::1.sync.aligned.b32 %0, %1;" :: "r"(tmem), "r"(ncols));
}
__device__ __forceinline__ void mma_f16_ss(uint32_t d, uint64_t ad, uint64_t bd, uint32_t idesc, uint32_t en) {
    asm volatile(
        "{\n\t.reg .pred p;\n\tsetp.ne.u32 p, %5, 0;\n\t"
        "tcgen05.mma.cta_group::1.kind::f16 [%0], %1, %2, %3, {%4,%4,%4,%4}, p;\n\t}"
        :: "r"(d), "l"(ad), "l"(bd), "r"(idesc), "r"(0u), "r"(en) : "memory");
}
__device__ __forceinline__ void tccommit(uint32_t mbar) {
    asm volatile("tcgen05.commit.cta_group::1.mbarrier::arrive::one.shared::cluster.b64 [%0];"
                 :: "r"(mbar) : "memory");
}
__device__ __forceinline__ void cpa16(uint32_t dst, const void* src) {
    asm volatile("cp.async.cg.shared.global [%0], [%1], 16;" :: "r"(dst), "l"(src) : "memory");
}
__device__ __forceinline__ void ldtm32(uint32_t* r, uint32_t addr) {
    asm volatile(
        "tcgen05.ld.sync.aligned.32x32b.x32.b32 "
        "{%0, %1, %2, %3, %4, %5, %6, %7, "
        " %8, %9, %10, %11, %12, %13, %14, %15, "
        " %16, %17, %18, %19, %20, %21, %22, %23, "
        " %24, %25, %26, %27, %28, %29, %30, %31}, [%32];"
        : "=r"(r[0]),  "=r"(r[1]),  "=r"(r[2]),  "=r"(r[3]),
          "=r"(r[4]),  "=r"(r[5]),  "=r"(r[6]),  "=r"(r[7]),
          "=r"(r[8]),  "=r"(r[9]),  "=r"(r[10]), "=r"(r[11]),
          "=r"(r[12]), "=r"(r[13]), "=r"(r[14]), "=r"(r[15]),
          "=r"(r[16]), "=r"(r[17]), "=r"(r[18]), "=r"(r[19]),
          "=r"(r[20]), "=r"(r[21]), "=r"(r[22]), "=r"(r[23]),
          "=r"(r[24]), "=r"(r[25]), "=r"(r[26]), "=r"(r[27]),
          "=r"(r[28]), "=r"(r[29]), "=r"(r[30]), "=r"(r[31])
        : "r"(addr));
}
#endif
#define SWZ(o)   ((o) ^ (((o) >> 3) & 0x70))
#define SWZ64(o) ((o) ^ (((o) >> 3) & 0x30))
__device__ __forceinline__ uint64_t mk_desc64(uint32_t addr) {
    return ((uint64_t)4 << 61) | ((uint64_t)1 << 46) | ((uint64_t)32 << 32) |
           ((uint64_t)1 << 16) | ((addr >> 4) & 0x3FFF);
}

// ---------------- weight fp32 -> fp16 convert ----------------
__global__ void k_convert(const float* __restrict__ Wup, const float* __restrict__ Wdown) {
    const size_t HALF = (size_t)NE * HID * DIM;
    size_t base = ((size_t)blockIdx.x * 256 + threadIdx.x) * 8;
    const float* src;
    __half* dst;
    size_t off;
    if (base < HALF) { src = Wup;   dst = g_wup; off = base; }
    else             { src = Wdown; dst = g_wdn; off = base - HALF; }
    float4 v0 = *(const float4*)(src + off);
    float4 v1 = *(const float4*)(src + off + 4);
    __half2 h[4];
    h[0] = __floats2half2_rn(v0.x, v0.y);
    h[1] = __floats2half2_rn(v0.z, v0.w);
    h[2] = __floats2half2_rn(v1.x, v1.y);
    h[3] = __floats2half2_rn(v1.z, v1.w);
    *(int4*)(dst + off) = *(int4*)h;
}

// ---------------- init ----------------
__global__ void k_init() {
    int i = threadIdx.x;
    if (i < NE) { g_count[i] = 0; g_cursor[i] = 0; }
}

// ---------------- router ----------------
__global__ void k_router(const float* __restrict__ x,
                         const float* __restrict__ Wr,
                         const float* __restrict__ br) {
    __shared__ float sW[NE * DIM];
    for (int i = threadIdx.x; i < NE * DIM; i += 256) sW[i] = Wr[i];
    __syncthreads();

    int warp = threadIdx.x >> 5, lane = threadIdx.x & 31;
    int t = blockIdx.x * 8 + warp;
    const float4* xr = (const float4*)(x + (size_t)t * DIM);

    float acc[NE];
#pragma unroll
    for (int e = 0; e < NE; e++) acc[e] = 0.f;
#pragma unroll
    for (int p = 0; p < 8; p++) {
        float4 v = xr[p * 32 + lane];
        int c = (p * 32 + lane) * 4;
#pragma unroll
        for (int e = 0; e < NE; e++) {
            const float* w = &sW[e * DIM + c];
            acc[e] += v.x * w[0] + v.y * w[1] + v.z * w[2] + v.w * w[3];
        }
    }
#pragma unroll
    for (int e = 0; e < NE; e++)
#pragma unroll
        for (int o = 16; o; o >>= 1) acc[e] += __shfl_xor_sync(0xffffffffu, acc[e], o);

    if (lane == 0) {
        int best = 0;
        float bv = acc[0] + br[0];
#pragma unroll
        for (int e = 1; e < NE; e++) {
            float v = acc[e] + br[e];
            if (v > bv) { bv = v; best = e; }
        }
        g_expert[t] = best;
        atomicAdd(&g_count[best], 1);
    }
}

// ---------------- scan ----------------
__global__ void k_scan() {
    if (threadIdx.x != 0) return;
    int o = 0;
    for (int e = 0; e < NE; e++) { g_off[e] = o; o += g_count[e]; }
    g_off[NE] = o;
    int t = 0;
    for (int e = 0; e < NE; e++) {
        int tiles = (g_count[e] + BM - 1) / BM;
        for (int m = 0; m < tiles; m += GM) {
            g_grp_e[t] = e;
            g_grp_r0[t] = g_off[e] + m * BM;
            int rem = tiles - m;
            g_grp_ng[t] = rem < GM ? rem : GM;
            t++;
        }
    }
    for (; t < MAXG; t++) g_grp_e[t] = -1;
    int tt = 0;
    for (int e = 0; e < NE; e++) {
        int tiles = (g_count[e] + BM - 1) / BM;
        for (int m = 0; m < tiles; m++) { g_tile_e[tt] = e; g_tile_r0[tt] = g_off[e] + m * BM; tt++; }
    }
    for (; tt < MAXT; tt++) g_tile_e[tt] = -1;
}

// ---------------- gather + fp32->fp16 ----------------
__global__ void k_gather(const float* __restrict__ x) {
    int gw = (blockIdx.x * blockDim.x + threadIdx.x) >> 5;
    int lane = threadIdx.x & 31;
    if (gw >= NTOK) return;
    int t = gw, e = g_expert[t];
    int slot = 0;
    if (lane == 0) {
        int r = atomicAdd(&g_cursor[e], 1);
        slot = g_off[e] + r;
        g_perm[slot] = t;
    }
    slot = __shfl_sync(0xffffffffu, slot, 0);
    const float4* src = (const float4*)(x + (size_t)t * DIM);
    __half2* dst = (__half2*)(g_xg + (size_t)slot * DIM);
#pragma unroll
    for (int p = 0; p < 8; p++) {
        float4 v = src[p * 32 + lane];
        dst[(p * 32 + lane) * 2]     = __floats2half2_rn(v.x, v.y);
        dst[(p * 32 + lane) * 2 + 1] = __floats2half2_rn(v.z, v.w);
    }
}

// ================= tcgen05 GEMM: GM=2 x BN=256, 5-buffer lookahead-3 pipeline =================
template<int KTOT, bool UP>
__global__ void __launch_bounds__(256, 1) k_gemm(const float* __restrict__ Wunused,
                                                 const float* __restrict__ bias,
                                                 float* __restrict__ out) {
#if TC5
    extern __shared__ char smem_raw[];
    char* smem = (char*)(((uintptr_t)smem_raw + 1023) & ~(uintptr_t)1023);
    const int NOUT = UP ? HID : DIM;

    int gi = blockIdx.y;
    int e = g_grp_e[gi];
    if (e < 0) return;
    int row0 = g_grp_r0[gi], ng = g_grp_ng[gi], row_end = g_off[e + 1];
    int n0 = blockIdx.x * BN;
    int tid = threadIdx.x, warp = tid >> 5, lane = tid & 31;
    uint32_t sb = smem_u32(smem);

    if (tid == 0) {
#pragma unroll
        for (int j = 0; j < STG; j++) mbar_init(sb + 8 * j, 1);
    }
    if (warp == 0) tmalloc(sb + 64, 512);
    __syncthreads();
    uint32_t tmem;
    asm volatile("ld.shared.b32 %0, [%1];" : "=r"(tmem) : "r"(sb + 64));

    const __half* Asrc = UP ? g_xg : g_h;
    const __half* Ag = Asrc + (size_t)row0 * KTOT;
    const __half* Bg = (UP ? g_wup : g_wdn) + (size_t)e * NOUT * KTOT + (size_t)n0 * KTOT;
    const uint32_t idesc = (1u << 4) | ((BN / 8) << 17) | ((BM / 16) << 24);
    const int SMA = 1024;

    auto LOAD = [&](int s, int buf) {
        uint32_t stBase = sb + SMA + buf * STAGE_BYTES;
#pragma unroll
        for (int g = 0; g < GM; g++) {
            if (g < ng) {
                const __half* As = Ag + (size_t)g * BM * KTOT + s * KC;
                uint32_t ab = stBase + g * 8192;
#pragma unroll
                for (int i = 0; i < 2; i++) {
                    int q = tid + i * 256;
                    int r = q >> 2, c = q & 3;
                    cpa16(ab + SWZ64((uint32_t)(r * 64 + c * 16)),
                          As + (size_t)r * KTOT + c * 8);
                }
            }
        }
        const __half* Bs = Bg + s * KC;
        uint32_t bb = stBase + A_ST;
#pragma unroll
        for (int i = 0; i < 4; i++) {
            int q = tid + i * 256;
            int r = q >> 2, c = q & 3;
            cpa16(bb + SWZ64((uint32_t)(r * 64 + c * 16)),
                  Bs + (size_t)r * KTOT + c * 8);
        }
    };

    const int NKC = KTOT / KC;           // UP: 32, DOWN: 128

#pragma unroll
    for (int p = 0; p < 3; p++) { LOAD(p, p); asm volatile("cp.async.commit_group;" ::: "memory"); }

    for (int s = 0; s < NKC; s++) {
        if (s >= 2) mbar_wait(sb + 8 * ((s - 2) % STG), (uint32_t)(((s - 2) / STG) & 1));
        if (s + 3 < NKC) LOAD(s + 3, (s + 3) % STG);
        asm volatile("cp.async.commit_group;" ::: "memory");
        asm volatile("cp.async.wait_group 3;" ::: "memory");
        asm volatile("fence.proxy.async.shared::cta;" ::: "memory");
        __syncthreads();

        if (warp == 0 && elect1()) {
            uint32_t stBase = sb + SMA + (s % STG) * STAGE_BYTES;
            uint64_t bd = mk_desc64(stBase + A_ST);
#pragma unroll
            for (int g = 0; g < GM; g++) {
                if (g < ng) {
                    uint64_t ad = mk_desc64(stBase + g * 8192);
#pragma unroll
                    for (int ks = 0; ks < 2; ks++) {
                        mma_f16_ss(tmem + g * BN, ad + ks * 2, bd + ks * 2, idesc,
                                   (uint32_t)((s | ks) != 0));
                    }
                }
            }
            tccommit(sb + 8 * (s % STG));
        }
    }
#pragma unroll
    for (int j = 0; j < STG; j++) {
        int sj = (NKC - 1) - ((NKC - 1 - j) % STG);
        mbar_wait(sb + 8 * j, (uint32_t)((sj / STG) & 1));
    }
    asm volatile("tcgen05.fence::after_thread_sync;" ::: "memory");

    // ---- epilogue: 4 warps per group, 8 col-blocks of 32 ----
    int g = warp >> 2;
    int sub = warp & 3;
    const float* bp = bias + (size_t)e * NOUT + n0;
    if (g < ng) {
        int row = row0 + g * BM + sub * 32 + lane;
        bool ok = row < row_end;
#pragma unroll
        for (int cb = 0; cb < 8; cb++) {
            uint32_t r[32];
            ldtm32(r, tmem + g * BN + cb * 32);
            asm volatile("tcgen05.wait::ld.sync.aligned;" ::: "memory");
            if (ok) {
                int col = cb * 32;
                if (UP) {
                    __half2 o[16];
#pragma unroll
                    for (int j = 0; j < 16; j++) {
                        float v0 = __uint_as_float(r[2 * j])     + bp[col + 2 * j];
                        float v1 = __uint_as_float(r[2 * j + 1]) + bp[col + 2 * j + 1];
                        v0 = v0 / (1.f + __expf(-v0));
                        v1 = v1 / (1.f + __expf(-v1));
                        o[j] = __floats2half2_rn(v0, v1);
                    }
                    int4* dst = (int4*)(g_h + (size_t)row * HID + n0 + col);
#pragma unroll
                    for (int q = 0; q < 4; q++) dst[q] = ((int4*)o)[q];
                } else {
                    int tok = g_perm[row];
                    float4* dst = (float4*)(out + (size_t)tok * DIM + n0 + col);
#pragma unroll
                    for (int q = 0; q < 8; q++) {
                        float4 ov;
                        ov.x = __uint_as_float(r[4 * q + 0]) + bp[col + 4 * q + 0];
                        ov.y = __uint_as_float(r[4 * q + 1]) + bp[col + 4 * q + 1];
                        ov.z = __uint_as_float(r[4 * q + 2]) + bp[col + 4 * q + 2];
                        ov.w = __uint_as_float(r[4 * q + 3]) + bp[col + 4 * q + 3];
                        dst[q] = ov;
                    }
                }
            }
        }
    }
    __syncthreads();
    if (warp == 0) tmdealloc(tmem, 512);
#endif
}

// ================= wmma fallback GEMMs (active only in non-'a' image) =================
__global__ __launch_bounds__(256, 2) void k_up(const float* __restrict__ Wup,
                                               const float* __restrict__ bup) {
#if !TC5
    __shared__ __align__(128) char smem_raw[4 * BM * LDSMW * sizeof(__half)];
    __half (*sA)[BM][LDSMW] = (__half (*)[BM][LDSMW])smem_raw;
    __half (*sB)[BM][LDSMW] = (__half (*)[BM][LDSMW])(smem_raw + 2 * BM * LDSMW * sizeof(__half));
    float* stage_all = (float*)smem_raw;

    int mt = blockIdx.y;
    int e = g_tile_e[mt];
    if (e < 0) return;
    int row0 = g_tile_r0[mt], row_end = g_off[e + 1];
    int n0 = blockIdx.x * BNW;
    int tid = threadIdx.x, warp = tid >> 5, lane = tid & 31;
    int wm = warp >> 2, wn = warp & 3;

    const __half* Ag = g_xg + (size_t)row0 * DIM;
    const float*  Bg = Wup + (size_t)e * HID * DIM + (size_t)n0 * DIM;

    wmma::fragment<wmma::accumulator, 16, 16, 16, float> c[4][2];
#pragma unroll
    for (int i = 0; i < 4; i++)
#pragma unroll
        for (int j = 0; j < 2; j++) wmma::fill_fragment(c[i][j], 0.f);

    int4 ra[2];
    float4 rb[4];

    auto LOADA = [&](int kt) {
#pragma unroll
        for (int i = 0; i < 2; i++) {
            int q = tid + i * 256, r = q >> 2, c8 = q & 3;
            ra[i] = *(const int4*)(Ag + (size_t)r * DIM + kt * BK + c8 * 8);
        }
    };
    auto LOADB = [&](int kt) {
#pragma unroll
        for (int i = 0; i < 4; i++) {
            int q = tid + i * 256, r = q >> 3, c4 = q & 7;
            rb[i] = *(const float4*)(Bg + (size_t)r * DIM + kt * BK + c4 * 4);
        }
    };
    auto STORE = [&](int buf) {
#pragma unroll
        for (int i = 0; i < 2; i++) {
            int q = tid + i * 256, r = q >> 2, c8 = q & 3;
            *(int4*)&sA[buf][r][c8 * 8] = ra[i];
        }
#pragma unroll
        for (int i = 0; i < 4; i++) {
            int q = tid + i * 256, r = q >> 3, c4 = q & 7;
            *(__half2*)&sB[buf][r][c4 * 4]     = __floats2half2_rn(rb[i].x, rb[i].y);
            *(__half2*)&sB[buf][r][c4 * 4 + 2] = __floats2half2_rn(rb[i].z, rb[i].w);
        }
    };
    auto COMP = [&](int buf) {
#pragma unroll
        for (int ks = 0; ks < 2; ks++) {
            wmma::fragment<wmma::matrix_a, 16, 16, 16, __half, wmma::row_major> a[4];
            wmma::fragment<wmma::matrix_b, 16, 16, 16, __half, wmma::col_major> b[2];
#pragma unroll
            for (int i = 0; i < 4; i++)
                wmma::load_matrix_sync(a[i], &sA[buf][wm * 64 + i * 16][ks * 16], LDSMW);
#pragma unroll
            for (int j = 0; j < 2; j++)
                wmma::load_matrix_sync(b[j], &sB[buf][wn * 32 + j * 16][ks * 16], LDSMW);
#pragma unroll
            for (int i = 0; i < 4; i++)
#pragma unroll
                for (int j = 0; j < 2; j++)
                    wmma::mma_sync(c[i][j], a[i], b[j], c[i][j]);
        }
    };

    LOADA(0); LOADB(0); STORE(0); __syncthreads();
    const int NK = DIM / BK;
    for (int kt = 1; kt < NK; kt++) {
        LOADA(kt); LOADB(kt);
        COMP((kt - 1) & 1);
        STORE(kt & 1);
        __syncthreads();
    }
    COMP((NK - 1) & 1);
    __syncthreads();

    float* st = stage_all + warp * 16 * 20;
#pragma unroll
    for (int i = 0; i < 4; i++)
#pragma unroll
        for (int j = 0; j < 2; j++) {
            wmma::store_matrix_sync(st, c[i][j], 20, wmma::mem_row_major);
            __syncwarp();
            int rr = lane >> 1, cbase = (lane & 1) * 8;
            int grow = row0 + wm * 64 + i * 16 + rr;
            if (grow < row_end) {
                int gcol = n0 + wn * 32 + j * 16 + cbase;
                __half2 o[4];
#pragma unroll
                for (int k2 = 0; k2 < 4; k2++) {
                    float v0 = st[rr * 20 + cbase + 2 * k2]     + bup[(size_t)e * HID + gcol + 2 * k2];
                    float v1 = st[rr * 20 + cbase + 2 * k2 + 1] + bup[(size_t)e * HID + gcol + 2 * k2 + 1];
                    v0 = v0 / (1.f + expf(-v0));
                    v1 = v1 / (1.f + expf(-v1));
                    o[k2] = __floats2half2_rn(v0, v1);
                }
                *(int4*)&g_h[(size_t)grow * HID + gcol] = *(int4*)o;
            }
            __syncwarp();
        }
#endif
}

__global__ __launch_bounds__(256, 2) void k_down(const float* __restrict__ Wdown,
                                                 const float* __restrict__ bdown,
                                                 float* __restrict__ out) {
#if !TC5
    __shared__ __align__(128) char smem_raw[4 * BM * LDSMW * sizeof(__half)];
    __half (*sA)[BM][LDSMW] = (__half (*)[BM][LDSMW])smem_raw;
    __half (*sB)[BM][LDSMW] = (__half (*)[BM][LDSMW])(smem_raw + 2 * BM * LDSMW * sizeof(__half));
    float* stage_all = (float*)smem_raw;

    int mt = blockIdx.y;
    int e = g_tile_e[mt];
    if (e < 0) return;
    int row0 = g_tile_r0[mt], row_end = g_off[e + 1];
    int n0 = blockIdx.x * BNW;
    int tid = threadIdx.x, warp = tid >> 5, lane = tid & 31;
    int wm = warp >> 2, wn = warp & 3;

    const __half* Ag = g_h + (size_t)row0 * HID;
    const float*  Bg = Wdown + (size_t)e * DIM * HID + (size_t)n0 * HID;

    wmma::fragment<wmma::accumulator, 16, 16, 16, float> c[4][2];
#pragma unroll
    for (int i = 0; i < 4; i++)
#pragma unroll
        for (int j = 0; j < 2; j++) wmma::fill_fragment(c[i][j], 0.f);

    int4 ra[2];
    float4 rb[4];

    auto LOADA = [&](int kt) {
#pragma unroll
        for (int i = 0; i < 2; i++) {
            int q = tid + i * 256, r = q >> 2, c8 = q & 3;
            ra[i] = *(const int4*)(Ag + (size_t)r * HID + kt * BK + c8 * 8);
        }
    };
    auto LOADB = [&](int kt) {
#pragma unroll
        for (int i = 0; i < 4; i++) {
            int q = tid + i * 256, r = q >> 3, c4 = q & 7;
            rb[i] = *(const float4*)(Bg + (size_t)r * HID + kt * BK + c4 * 4);
        }
    };
    auto STORE = [&](int buf) {
#pragma unroll
        for (int i = 0; i < 2; i++) {
            int q = tid + i * 256, r = q >> 2, c8 = q & 3;
            *(int4*)&sA[buf][r][c8 * 8] = ra[i];
        }
#pragma unroll
        for (int i = 0; i < 4; i++) {
            int q = tid + i * 256, r = q >> 3, c4 = q & 7;
            *(__half2*)&sB[buf][r][c4 * 4]     = __floats2half2_rn(rb[i].x, rb[i].y);
            *(__half2*)&sB[buf][r][c4 * 4 + 2] = __floats2half2_rn(rb[i].z, rb[i].w);
        }
    };
    auto COMP = [&](int buf) {
#pragma unroll
        for (int ks = 0; ks < 2; ks++) {
            wmma::fragment<wmma::matrix_a, 16, 16, 16, __half, wmma::row_major> a[4];
            wmma::fragment<wmma::matrix_b, 16, 16, 16, __half, wmma::col_major> b[2];
#pragma unroll
            for (int i = 0; i < 4; i++)
                wmma::load_matrix_sync(a[i], &sA[buf][wm * 64 + i * 16][ks * 16], LDSMW);
#pragma unroll
            for (int j = 0; j < 2; j++)
                wmma::load_matrix_sync(b[j], &sB[buf][wn * 32 + j * 16][ks * 16], LDSMW);
#pragma unroll
            for (int i = 0; i < 4; i++)
#pragma unroll
                for (int j = 0; j < 2; j++)
                    wmma::mma_sync(c[i][j], a[i], b[j], c[i][j]);
        }
    };

    LOADA(0); LOADB(0); STORE(0); __syncthreads();
    const int NK = HID / BK;
    for (int kt = 1; kt < NK; kt++) {
        LOADA(kt); LOADB(kt);
        COMP((kt - 1) & 1);
        STORE(kt & 1);
        __syncthreads();
    }
    COMP((NK - 1) & 1);
    __syncthreads();

    float* st = stage_all + warp * 16 * 20;
#pragma unroll
    for (int i = 0; i < 4; i++)
#pragma unroll
        for (int j = 0; j < 2; j++) {
            wmma::store_matrix_sync(st, c[i][j], 20, wmma::mem_row_major);
            __syncwarp();
            int rr = lane >> 1, cbase = (lane & 1) * 8;
            int grow = row0 + wm * 64 + i * 16 + rr;
            if (grow < row_end) {
                int tok = g_perm[grow];
                int gcol = n0 + wn * 32 + j * 16 + cbase;
                float4 o0, o1;
                o0.x = st[rr * 20 + cbase + 0] + bdown[(size_t)e * DIM + gcol + 0];
                o0.y = st[rr * 20 + cbase + 1] + bdown[(size_t)e * DIM + gcol + 1];
                o0.z = st[rr * 20 + cbase + 2] + bdown[(size_t)e * DIM + gcol + 2];
                o0.w = st[rr * 20 + cbase + 3] + bdown[(size_t)e * DIM + gcol + 3];
                o1.x = st[rr * 20 + cbase + 4] + bdown[(size_t)e * DIM + gcol + 4];
                o1.y = st[rr * 20 + cbase + 5] + bdown[(size_t)e * DIM + gcol + 5];
                o1.z = st[rr * 20 + cbase + 6] + bdown[(size_t)e * DIM + gcol + 6];
                o1.w = st[rr * 20 + cbase + 7] + bdown[(size_t)e * DIM + gcol + 7];
                *(float4*)&out[(size_t)tok * DIM + gcol]     = o0;
                *(float4*)&out[(size_t)tok * DIM + gcol + 4] = o1;
            }
            __syncwarp();
        }
#endif
}

// ---------------- launcher ----------------
extern "C" void kernel_launch(void* const* d_in, const int* in_sizes, int n_in,
                              void* d_out, int out_size) {
    const float* x     = (const float*)d_in[0];
    const float* Wr    = (const float*)d_in[1];
    const float* br    = (const float*)d_in[2];
    const float* Wup   = (const float*)d_in[3];
    const float* bup   = (const float*)d_in[4];
    const float* Wdown = (const float*)d_in[5];
    const float* bdown = (const float*)d_in[6];
    float* out = (float*)d_out;

    cudaFuncSetAttribute(k_gemm<DIM, true>,  cudaFuncAttributeMaxDynamicSharedMemorySize, SMEM_BYTES);
    cudaFuncSetAttribute(k_gemm<HID, false>, cudaFuncAttributeMaxDynamicSharedMemorySize, SMEM_BYTES);

    const size_t TOTW = 2 * (size_t)NE * HID * DIM;
    k_convert<<<(int)(TOTW / 2048), 256>>>(Wup, Wdown);
    k_init<<<1, 32>>>();
    k_router<<<NTOK / 8, 256>>>(x, Wr, br);
    k_scan<<<1, 1>>>();
    k_gather<<<NTOK / 8, 256>>>(x);
    k_up<<<dim3(HID / BNW, MAXT), 256>>>(Wup, bup);                                     // empty in 'a'
    k_gemm<DIM, true ><<<dim3(HID / BN, MAXG), 256, SMEM_BYTES>>>(Wup, bup, nullptr);
    k_gemm<HID, false><<<dim3(DIM / BN, MAXG), 256, SMEM_BYTES>>>(Wdown, bdown, out);
    k_down<<<dim3(DIM / BNW, MAXT), 256>>>(Wdown, bdown, out);                          // empty in 'a'
}